// round 5
// baseline (speedup 1.0000x reference)
#include <cuda_runtime.h>
#include <cuda_fp16.h>
#include <math.h>
#include <cstdint>

#define B_  8
#define T_  2048
#define E_  1024
#define H_  128
#define BT_ (B_*T_)

// split operands (allocation-free scratch)
__device__ __half g_x1[BT_*E_], g_x2[BT_*E_];       // x split, [tok][k]
__device__ __half g_w1[3*H_*E_], g_w2[3*H_*E_];     // W^T split, [sel][n][k]
__device__ __half g_qh1[BT_*H_], g_qh2[BT_*H_];     // q*sqrt(T) split, [tok][h]
__device__ __half g_kh1[BT_*H_], g_kh2[BT_*H_];     // k split, [tok][h]
__device__ __half g_vh1[BT_*H_], g_vh2[BT_*H_];     // v split, [tok][h]
__device__ __half g_vt1[B_*H_*T_], g_vt2[B_*H_*T_]; // v^T split, [b][h][tok]

// ---------------------------------------------------------------------------
__device__ __forceinline__ void split2(float x, float y, uint32_t& hi, uint32_t& lo) {
    __half2 h = __floats2half2_rn(x, y);
    float2 f = __half22float2(h);
    __half2 l = __floats2half2_rn(x - f.x, y - f.y);
    hi = *(uint32_t*)&h; lo = *(uint32_t*)&l;
}

__device__ __forceinline__ void mma16(float* d, const uint32_t* a, const uint32_t* b) {
    asm volatile(
        "mma.sync.aligned.m16n8k16.row.col.f32.f16.f16.f32 "
        "{%0,%1,%2,%3}, {%4,%5,%6,%7}, {%8,%9}, {%0,%1,%2,%3};"
        : "+f"(d[0]), "+f"(d[1]), "+f"(d[2]), "+f"(d[3])
        : "r"(a[0]), "r"(a[1]), "r"(a[2]), "r"(a[3]), "r"(b[0]), "r"(b[1]));
}

// ---------------------------------------------------------------------------
// x -> fp16 split pair
// ---------------------------------------------------------------------------
__global__ void split_x(const float* __restrict__ x)
{
    const int i = blockIdx.x * 256 + threadIdx.x;   // 8 floats per thread
    const float4* xv = (const float4*)x;
    uint32_t* o1 = (uint32_t*)g_x1;
    uint32_t* o2 = (uint32_t*)g_x2;
#pragma unroll
    for (int p = 0; p < 2; p++) {
        float4 f = xv[(size_t)i * 2 + p];
        uint32_t h, l;
        split2(f.x, f.y, h, l);
        o1[(size_t)i*4 + p*2]     = h;  o2[(size_t)i*4 + p*2]     = l;
        split2(f.z, f.w, h, l);
        o1[(size_t)i*4 + p*2 + 1] = h;  o2[(size_t)i*4 + p*2 + 1] = l;
    }
}

// ---------------------------------------------------------------------------
// W -> W^T, split to halves.  grid (E/32, H/32, 3), 256 thr
// ---------------------------------------------------------------------------
__global__ void prep_w(const float* __restrict__ Wq,
                       const float* __restrict__ Wk,
                       const float* __restrict__ Wv)
{
    __shared__ float tile[32][33];
    const int sel = blockIdx.z;
    const float* __restrict__ W = (sel == 0) ? Wq : (sel == 1) ? Wk : Wv;
    const int k0 = blockIdx.x * 32, n0 = blockIdx.y * 32;
    const int tx = threadIdx.x & 31, ty = threadIdx.x >> 5;
#pragma unroll
    for (int i = 0; i < 4; i++)
        tile[ty + 8*i][tx] = W[(size_t)(k0 + ty + 8*i) * H_ + n0 + tx];
    __syncthreads();
    uint32_t* w1 = (uint32_t*)g_w1;
    uint32_t* w2 = (uint32_t*)g_w2;
#pragma unroll
    for (int r = 0; r < 2; r++) {
        int slot = r * 256 + threadIdx.x;
        int ni = slot >> 4, kp = slot & 15;
        float a = tile[2*kp][ni], b = tile[2*kp + 1][ni];
        uint32_t h, l;
        split2(a, b, h, l);
        size_t o = ((size_t)(sel * H_ + n0 + ni) * E_ + k0 + 2*kp) >> 1;
        w1[o] = h; w2[o] = l;
    }
}

// ---------------------------------------------------------------------------
// Projection, fp16 split MMA. CTA 128x128, 8 warps (4m x 2n), warp 32x64.
// K chunks of 32, LDG->reg double buffer.
// ---------------------------------------------------------------------------
#define PJS 40                // smem half-stride
#define PJ_BUF 20480          // halves per buffer (4 arrays x 128*40)
#define PJ_SMEM (2 * PJ_BUF * 2)   // 81920 B

__global__ __launch_bounds__(256, 1) void proj_tc()
{
    extern __shared__ __half sh[];
    const int t = threadIdx.x;
    const int wid = t >> 5, lane = t & 31;
    const int wm = wid >> 1, wn = wid & 1;
    const int g = lane >> 2, tg = lane & 3;
    const int sel = blockIdx.y;
    const int m0 = blockIdx.x * 128;

    const uint4* xs1 = (const uint4*)g_x1;
    const uint4* xs2 = (const uint4*)g_x2;
    const uint4* ws1 = (const uint4*)(g_w1 + (size_t)sel * H_ * E_);
    const uint4* ws2 = (const uint4*)(g_w2 + (size_t)sel * H_ * E_);

    float acc[2][8][4];
#pragma unroll
    for (int mi = 0; mi < 2; mi++)
#pragma unroll
        for (int ni = 0; ni < 8; ni++)
#pragma unroll
            for (int r = 0; r < 4; r++) acc[mi][ni][r] = 0.f;

    const int lrow = t >> 2, lc8 = t & 3;    // loader mapping (2 passes)
    uint4 px1[2], px2[2], pw1[2], pw2[2];

    auto fetch = [&](int c) {
#pragma unroll
        for (int r = 0; r < 2; r++) {
            int row = (r * 256 + t) >> 2, c8 = lc8;
            size_t xo = (size_t)(m0 + row) * 128 + c * 4 + c8;
            size_t wo = (size_t)row * 128 + c * 4 + c8;
            px1[r] = xs1[xo]; px2[r] = xs2[xo];
            pw1[r] = ws1[wo]; pw2[r] = ws2[wo];
        }
    };
    auto store = [&](int p) {
        uint4* X1 = (uint4*)(sh + p * PJ_BUF);
        uint4* X2 = (uint4*)(sh + p * PJ_BUF + 5120);
        uint4* W1 = (uint4*)(sh + p * PJ_BUF + 10240);
        uint4* W2 = (uint4*)(sh + p * PJ_BUF + 15360);
#pragma unroll
        for (int r = 0; r < 2; r++) {
            int row = (r * 256 + t) >> 2;
            int d = row * 5 + lc8;
            X1[d] = px1[r]; X2[d] = px2[r];
            W1[d] = pw1[r]; W2[d] = pw2[r];
        }
    };

    fetch(0); store(0);
    __syncthreads();

    for (int c = 0; c < 32; c++) {
        const int p = c & 1;
        if (c < 31) fetch(c + 1);

        const __half* X1 = sh + p * PJ_BUF;
        const __half* X2 = X1 + 5120;
        const __half* W1 = X1 + 10240;
        const __half* W2 = X1 + 15360;
#define H2_(ptr, off) (*(const uint32_t*)&(ptr)[off])
#pragma unroll
        for (int s = 0; s < 2; s++) {
            uint32_t a1[2][4], a2[2][4];
#pragma unroll
            for (int mi = 0; mi < 2; mi++) {
                int r = wm * 32 + mi * 16 + g;
                int o = r * PJS + s * 16 + 2 * tg;
                a1[mi][0] = H2_(X1, o);            a1[mi][1] = H2_(X1, o + 8*PJS);
                a1[mi][2] = H2_(X1, o + 8);        a1[mi][3] = H2_(X1, o + 8*PJS + 8);
                a2[mi][0] = H2_(X2, o);            a2[mi][1] = H2_(X2, o + 8*PJS);
                a2[mi][2] = H2_(X2, o + 8);        a2[mi][3] = H2_(X2, o + 8*PJS + 8);
            }
#pragma unroll
            for (int ni = 0; ni < 8; ni++) {
                int bn = wn * 64 + ni * 8 + g;
                int bo = bn * PJS + s * 16 + 2 * tg;
                uint32_t b1[2] = {H2_(W1, bo), H2_(W1, bo + 8)};
                uint32_t b2[2] = {H2_(W2, bo), H2_(W2, bo + 8)};
#pragma unroll
                for (int mi = 0; mi < 2; mi++) {
                    mma16(acc[mi][ni], a1[mi], b1);
                    mma16(acc[mi][ni], a1[mi], b2);
                    if (sel < 2) mma16(acc[mi][ni], a2[mi], b1);
                }
            }
        }
        if (c < 31) {
            __syncthreads();
            store(p ^ 1);
            __syncthreads();
        }
    }

    // epilogue: scale (q only), split, store halves
    uint32_t* o1 = (uint32_t*)((sel == 0) ? g_qh1 : (sel == 1) ? g_kh1 : g_vh1);
    uint32_t* o2 = (uint32_t*)((sel == 0) ? g_qh2 : (sel == 1) ? g_kh2 : g_vh2);
    const float sc = (sel == 0) ? 45.25483399593904f : 1.f;
#pragma unroll
    for (int mi = 0; mi < 2; mi++) {
        int row = m0 + wm * 32 + mi * 16 + g;
#pragma unroll
        for (int ni = 0; ni < 8; ni++) {
            int col = wn * 64 + ni * 8 + tg * 2;
            uint32_t h, l;
            split2(acc[mi][ni][0] * sc, acc[mi][ni][1] * sc, h, l);
            o1[(size_t)row * 64 + (col >> 1)] = h;
            o2[(size_t)row * 64 + (col >> 1)] = l;
            split2(acc[mi][ni][2] * sc, acc[mi][ni][3] * sc, h, l);
            o1[(size_t)(row + 8) * 64 + (col >> 1)] = h;
            o2[(size_t)(row + 8) * 64 + (col >> 1)] = l;
        }
    }
}

// ---------------------------------------------------------------------------
// V transpose per batch: [tok][h] -> [h][tok].  grid (T/32, H/32, B), 256 thr
// ---------------------------------------------------------------------------
__global__ void prep_vt()
{
    __shared__ __half t1[32][33], t2[32][33];
    const int b = blockIdx.z;
    const int t0 = blockIdx.x * 32, h0 = blockIdx.y * 32;
    const int tx = threadIdx.x & 31, ty = threadIdx.x >> 5;
#pragma unroll
    for (int i = 0; i < 4; i++) {
        size_t s = (size_t)(b * T_ + t0 + ty + 8*i) * H_ + h0 + tx;
        t1[ty + 8*i][tx] = g_vh1[s];
        t2[ty + 8*i][tx] = g_vh2[s];
    }
    __syncthreads();
#pragma unroll
    for (int i = 0; i < 4; i++) {
        size_t d = (size_t)(b * H_ + h0 + ty + 8*i) * T_ + t0 + tx;
        g_vt1[d] = t1[tx][ty + 8*i];
        g_vt2[d] = t2[tx][ty + 8*i];
    }
}

// ---------------------------------------------------------------------------
// Flash attention, fp16 MMA. BQ=64, BK=128. 8 warps (4m x 2n). Q in regs.
// QK^T: q1k1+q1k2+q2k1.  PV: p*(v1) + p*(v2).
// ---------------------------------------------------------------------------
#define AST 136               // smem half-stride
#define SQ1 0
#define SQ2 8704
#define SK1 17408
#define SK2 34816
#define SV1 52224
#define SV2 69632
#define SP_ 87040
#define A_HALVES 95744
#define A_SMEM (A_HALVES*2 + 256*4)   // 192512 B

__global__ __launch_bounds__(256, 1) void attn_tc(float* __restrict__ out)
{
    extern __shared__ __half sh[];
    float* smax = (float*)(sh + A_HALVES);
    float* ssum = smax + 128;

    const int t = threadIdx.x;
    const int wid = t >> 5, lane = t & 31;
    const int wm = wid >> 1, wn = wid & 1;
    const int g = lane >> 2, tg = lane & 3;
    const int qt = (int)gridDim.x - 1 - (int)blockIdx.x;
    const int b = blockIdx.y;
    const size_t btok = (size_t)b * T_;

    // load Q tile (64 x 128 halves x2 splits) into smem
    {
        const int row = t >> 2, cb = (t & 3) * 4;   // 4 uint4 per thread per split
        const uint4* q1 = (const uint4*)g_qh1;
        const uint4* q2 = (const uint4*)g_qh2;
        uint4* d1 = (uint4*)(sh + SQ1);
        uint4* d2 = (uint4*)(sh + SQ2);
#pragma unroll
        for (int p = 0; p < 4; p++) {
            size_t s = (btok + qt * 64 + row) * 16 + cb + p;
            d1[row * 17 + cb + p] = q1[s];
            d2[row * 17 + cb + p] = q2[s];
        }
    }
    __syncthreads();

    // Q fragments -> registers
    uint32_t qa1[8][4], qa2[8][4];
    {
        const int r = wm * 16 + g;
#pragma unroll
        for (int s = 0; s < 8; s++) {
            int o = r * AST + s * 16 + 2 * tg;
            qa1[s][0] = H2_(sh, SQ1 + o);           qa1[s][1] = H2_(sh, SQ1 + o + 8*AST);
            qa1[s][2] = H2_(sh, SQ1 + o + 8);       qa1[s][3] = H2_(sh, SQ1 + o + 8*AST + 8);
            qa2[s][0] = H2_(sh, SQ2 + o);           qa2[s][1] = H2_(sh, SQ2 + o + 8*AST);
            qa2[s][2] = H2_(sh, SQ2 + o + 8);       qa2[s][3] = H2_(sh, SQ2 + o + 8*AST + 8);
        }
    }

    float of[8][4];
#pragma unroll
    for (int ni = 0; ni < 8; ni++)
#pragma unroll
        for (int r = 0; r < 4; r++) of[ni][r] = 0.f;
    float mrun0 = -INFINITY, mrun1 = -INFINITY;
    float lrun0 = 0.f, lrun1 = 0.f;

    const int r0 = wm * 16 + g, r1 = r0 + 8;
    const int nkt = qt / 2 + 1;

    for (int kt = 0; kt < nkt; kt++) {
        __syncthreads();
        // load K (split x2) and V^T (split x2): 128 rows x 16 uint4 each
        {
            const int row = t >> 1, cb = (t & 1) * 8;  // 8 uint4 per thread per array
            const uint4* k1 = (const uint4*)g_kh1;
            const uint4* k2 = (const uint4*)g_kh2;
            const uint4* v1 = (const uint4*)g_vt1;
            const uint4* v2 = (const uint4*)g_vt2;
            uint4* dk1 = (uint4*)(sh + SK1);
            uint4* dk2 = (uint4*)(sh + SK2);
            uint4* dv1 = (uint4*)(sh + SV1);
            uint4* dv2 = (uint4*)(sh + SV2);
            size_t ks = (btok + kt * 128 + row) * 16 + cb;
            size_t vs = ((size_t)(b * H_ + row) * T_ + kt * 128) / 8 + cb;
#pragma unroll
            for (int p = 0; p < 8; p++) {
                dk1[row * 17 + cb + p] = k1[ks + p];
                dk2[row * 17 + cb + p] = k2[ks + p];
                dv1[row * 17 + cb + p] = v1[vs + p];
                dv2[row * 17 + cb + p] = v2[vs + p];
            }
        }
        __syncthreads();

        // S = Q K^T (64 x 128)
        float sf[8][4];
#pragma unroll
        for (int ni = 0; ni < 8; ni++)
#pragma unroll
            for (int r = 0; r < 4; r++) sf[ni][r] = 0.f;
#pragma unroll
        for (int s = 0; s < 8; s++) {
#pragma unroll
            for (int ni = 0; ni < 8; ni++) {
                int bn = wn * 64 + ni * 8 + g;
                int bo = bn * AST + s * 16 + 2 * tg;
                uint32_t b1[2] = {H2_(sh, SK1 + bo), H2_(sh, SK1 + bo + 8)};
                uint32_t b2[2] = {H2_(sh, SK2 + bo), H2_(sh, SK2 + bo + 8)};
                mma16(sf[ni], qa1[s], b1);
                mma16(sf[ni], qa1[s], b2);
                mma16(sf[ni], qa2[s], b1);
            }
        }

        // causal mask on last tile
        if (kt == nkt - 1) {
            int grow = qt * 64 + r0;
#pragma unroll
            for (int ni = 0; ni < 8; ni++) {
                int col = kt * 128 + wn * 64 + ni * 8 + tg * 2;
                if (col     > grow)     sf[ni][0] = -INFINITY;
                if (col + 1 > grow)     sf[ni][1] = -INFINITY;
                if (col     > grow + 8) sf[ni][2] = -INFINITY;
                if (col + 1 > grow + 8) sf[ni][3] = -INFINITY;
            }
        }

        // row max
        float pm0 = -INFINITY, pm1 = -INFINITY;
#pragma unroll
        for (int ni = 0; ni < 8; ni++) {
            pm0 = fmaxf(pm0, fmaxf(sf[ni][0], sf[ni][1]));
            pm1 = fmaxf(pm1, fmaxf(sf[ni][2], sf[ni][3]));
        }
        pm0 = fmaxf(pm0, __shfl_xor_sync(0xffffffffu, pm0, 1));
        pm0 = fmaxf(pm0, __shfl_xor_sync(0xffffffffu, pm0, 2));
        pm1 = fmaxf(pm1, __shfl_xor_sync(0xffffffffu, pm1, 1));
        pm1 = fmaxf(pm1, __shfl_xor_sync(0xffffffffu, pm1, 2));
        if (tg == 0) { smax[wn * 64 + r0] = pm0; smax[wn * 64 + r1] = pm1; }
        __syncthreads();

        float m0n = fmaxf(mrun0, fmaxf(smax[r0], smax[64 + r0]));
        float m1n = fmaxf(mrun1, fmaxf(smax[r1], smax[64 + r1]));
        float f0 = __expf(mrun0 - m0n);
        float f1 = __expf(mrun1 - m1n);
        mrun0 = m0n; mrun1 = m1n;

        // exp + partial sums + P store (fp16)
        float ps0 = 0.f, ps1 = 0.f;
#pragma unroll
        for (int ni = 0; ni < 8; ni++) {
            float e0 = __expf(sf[ni][0] - m0n);
            float e1 = __expf(sf[ni][1] - m0n);
            float e2 = __expf(sf[ni][2] - m1n);
            float e3 = __expf(sf[ni][3] - m1n);
            ps0 += e0 + e1; ps1 += e2 + e3;
            int col = wn * 64 + ni * 8 + tg * 2;
            __half2 p01 = __floats2half2_rn(e0, e1);
            __half2 p23 = __floats2half2_rn(e2, e3);
            *(uint32_t*)&sh[SP_ + r0 * AST + col] = *(uint32_t*)&p01;
            *(uint32_t*)&sh[SP_ + r1 * AST + col] = *(uint32_t*)&p23;
        }
        ps0 += __shfl_xor_sync(0xffffffffu, ps0, 1);
        ps0 += __shfl_xor_sync(0xffffffffu, ps0, 2);
        ps1 += __shfl_xor_sync(0xffffffffu, ps1, 1);
        ps1 += __shfl_xor_sync(0xffffffffu, ps1, 2);
        if (tg == 0) { ssum[wn * 64 + r0] = ps0; ssum[wn * 64 + r1] = ps1; }

        // rescale O
#pragma unroll
        for (int ni = 0; ni < 8; ni++) {
            of[ni][0] *= f0; of[ni][1] *= f0;
            of[ni][2] *= f1; of[ni][3] *= f1;
        }
        __syncthreads();
        lrun0 = lrun0 * f0 + ssum[r0] + ssum[64 + r0];
        lrun1 = lrun1 * f1 + ssum[r1] + ssum[64 + r1];

        // O += P V
#pragma unroll
        for (int s = 0; s < 8; s++) {
            uint32_t pa[4];
            int po = r0 * AST + s * 16 + 2 * tg;
            pa[0] = H2_(sh, SP_ + po);
            pa[1] = H2_(sh, SP_ + po + 8*AST);
            pa[2] = H2_(sh, SP_ + po + 8);
            pa[3] = H2_(sh, SP_ + po + 8*AST + 8);
#pragma unroll
            for (int ni = 0; ni < 8; ni++) {
                int bn = wn * 64 + ni * 8 + g;
                int bo = bn * AST + s * 16 + 2 * tg;
                uint32_t b1[2] = {H2_(sh, SV1 + bo), H2_(sh, SV1 + bo + 8)};
                uint32_t b2[2] = {H2_(sh, SV2 + bo), H2_(sh, SV2 + bo + 8)};
                mma16(of[ni], pa, b1);
                mma16(of[ni], pa, b2);
            }
        }
    }

    // epilogue
    float inv0 = 1.f / lrun0, inv1 = 1.f / lrun1;
    size_t grow = btok * H_ + (size_t)(qt * 64 + r0) * H_;
#pragma unroll
    for (int ni = 0; ni < 8; ni++) {
        int col = wn * 64 + ni * 8 + tg * 2;
        *(float2*)&out[grow + col] =
            make_float2(of[ni][0] * inv0, of[ni][1] * inv0);
        *(float2*)&out[grow + 8 * H_ + col] =
            make_float2(of[ni][2] * inv1, of[ni][3] * inv1);
    }
}

// ---------------------------------------------------------------------------
extern "C" void kernel_launch(void* const* d_in, const int* in_sizes, int n_in,
                              void* d_out, int out_size)
{
    const float* x  = (const float*)d_in[0];
    const float* Wq = (const float*)d_in[1];
    const float* Wk = (const float*)d_in[2];
    const float* Wv = (const float*)d_in[3];
    float* out = (float*)d_out;

    split_x<<<BT_ * E_ / 2048, 256>>>(x);
    prep_w<<<dim3(E_/32, H_/32, 3), 256>>>(Wq, Wk, Wv);

    cudaFuncSetAttribute(proj_tc,
                         cudaFuncAttributeMaxDynamicSharedMemorySize, PJ_SMEM);
    proj_tc<<<dim3(BT_/128, 3), 256, PJ_SMEM>>>();

    prep_vt<<<dim3(T_/32, H_/32, B_), 256>>>();

    cudaFuncSetAttribute(attn_tc,
                         cudaFuncAttributeMaxDynamicSharedMemorySize, A_SMEM);
    attn_tc<<<dim3(T_/64, B_), 256, A_SMEM>>>(out);
}

// round 6
// speedup vs baseline: 1.4611x; 1.4611x over previous
#include <cuda_runtime.h>
#include <math.h>
#include <cstdint>

#define B_  8
#define T_  2048
#define E_  1024
#define H_  128
#define BT_ (B_*T_)

// scratch (allocation-free: __device__ globals)
__device__ float g_q[BT_*H_];
__device__ float g_k[BT_*H_];
__device__ float g_v[BT_*H_];
__device__ float g_wt[3*H_*E_];   // W^T: [3][128 n][1024 k]

// ---------------------------------------------------------------------------
__device__ __forceinline__ float tf32r(float x) {
    float r; asm("cvt.rna.tf32.f32 %0, %1;" : "=f"(r) : "f"(x)); return r;
}

__device__ __forceinline__ void mma8(float* d, const uint32_t* a, const uint32_t* b) {
    asm volatile(
        "mma.sync.aligned.m16n8k8.row.col.f32.tf32.tf32.f32 "
        "{%0,%1,%2,%3}, {%4,%5,%6,%7}, {%8,%9}, {%0,%1,%2,%3};"
        : "+f"(d[0]), "+f"(d[1]), "+f"(d[2]), "+f"(d[3])
        : "r"(a[0]), "r"(a[1]), "r"(a[2]), "r"(a[3]), "r"(b[0]), "r"(b[1]));
}

// ---------------------------------------------------------------------------
// W transpose: Wt[n][k] = W[k][n]   (1024x128 -> 128x1024), x3 weights
// ---------------------------------------------------------------------------
__global__ void transpose_w(const float* __restrict__ Wq,
                            const float* __restrict__ Wk,
                            const float* __restrict__ Wv)
{
    __shared__ float tile[32][33];
    const int sel = blockIdx.z;
    const float* __restrict__ W = (sel == 0) ? Wq : (sel == 1) ? Wk : Wv;
    float* wt = g_wt + (size_t)sel * H_ * E_;
    const int k0 = blockIdx.x * 32, n0 = blockIdx.y * 32;
    const int tx = threadIdx.x & 31, ty = threadIdx.x >> 5;
#pragma unroll
    for (int i = 0; i < 4; i++)
        tile[ty + 8*i][tx] = W[(size_t)(k0 + ty + 8*i) * H_ + n0 + tx];
    __syncthreads();
#pragma unroll
    for (int i = 0; i < 4; i++)
        wt[(size_t)(n0 + ty + 8*i) * E_ + k0 + tx] = tile[tx][ty + 8*i];
}

// ---------------------------------------------------------------------------
// Projection: out = x @ W  via mma.sync tf32, 3xTF32 split (2 terms for V).
// CTA 64x128, 8 warps (2m x 4n), warp tile 32x32. K chunks of 32.
// LDG->reg prefetch of next chunk overlaps global latency with MMA.
// ---------------------------------------------------------------------------
#define PJ_SMEM ((2*64*36 + 2*128*36) * 4)   // 55296 B

__global__ __launch_bounds__(256, 2) void proj_tc(const float* __restrict__ x)
{
    extern __shared__ float sm[];
    float* Ah = sm;                   // [64][36]
    float* Al = Ah + 64*36;
    float* Bh = Al + 64*36;           // [128][36]  (n-major: row n holds 32 k)
    float* Bl = Bh + 128*36;
    const uint32_t* Ahu = (const uint32_t*)Ah;
    const uint32_t* Alu = (const uint32_t*)Al;
    const uint32_t* Bhu = (const uint32_t*)Bh;
    const uint32_t* Blu = (const uint32_t*)Bl;

    const int t    = threadIdx.x;
    const int wid  = t >> 5, lane = t & 31;
    const int wm   = wid >> 2, wn = wid & 3;
    const int g    = lane >> 2, tg = lane & 3;
    const int sel  = blockIdx.y;
    const int m0   = blockIdx.x * 64;

    const float* __restrict__ wt = g_wt + (size_t)sel * (H_ * E_);
    float* outp = (sel == 0) ? g_q : (sel == 1) ? g_k : g_v;

    float acc[2][4][4];
#pragma unroll
    for (int mi = 0; mi < 2; mi++)
#pragma unroll
        for (int ni = 0; ni < 4; ni++)
#pragma unroll
            for (int r = 0; r < 4; r++) acc[mi][ni][r] = 0.f;

    const int arow = t >> 3, ac4 = t & 7;          // A loader (64x8 f4, 2/thr)
    float4 fa[2], fb[4];

    auto fetch = [&](int c) {
        const int k0 = c * 32;
#pragma unroll
        for (int p = 0; p < 2; p++) {
            int row = (p * 256 + t) >> 3;
            fa[p] = *(const float4*)&x[(size_t)(m0 + row) * E_ + k0 + ac4 * 4];
        }
#pragma unroll
        for (int p = 0; p < 4; p++) {
            int row = (p * 256 + t) >> 3;
            fb[p] = *(const float4*)&wt[(size_t)row * E_ + k0 + ac4 * 4];
        }
    };
    auto store = [&]() {
#pragma unroll
        for (int p = 0; p < 2; p++) {
            int row = (p * 256 + t) >> 3;
            float4 v = fa[p];
            float4 h = {tf32r(v.x), tf32r(v.y), tf32r(v.z), tf32r(v.w)};
            float4 l = {tf32r(v.x - h.x), tf32r(v.y - h.y),
                        tf32r(v.z - h.z), tf32r(v.w - h.w)};
            *(float4*)&Ah[row * 36 + ac4 * 4] = h;
            *(float4*)&Al[row * 36 + ac4 * 4] = l;
        }
#pragma unroll
        for (int p = 0; p < 4; p++) {
            int row = (p * 256 + t) >> 3;
            float4 v = fb[p];
            float4 h = {tf32r(v.x), tf32r(v.y), tf32r(v.z), tf32r(v.w)};
            float4 l = {tf32r(v.x - h.x), tf32r(v.y - h.y),
                        tf32r(v.z - h.z), tf32r(v.w - h.w)};
            *(float4*)&Bh[row * 36 + ac4 * 4] = h;
            *(float4*)&Bl[row * 36 + ac4 * 4] = l;
        }
    };

    fetch(0);
    store();
    __syncthreads();

    for (int c = 0; c < 32; c++) {
        if (c < 31) fetch(c + 1);

#pragma unroll
        for (int ks = 0; ks < 4; ks++) {
            uint32_t ah[2][4], al[2][4];
#pragma unroll
            for (int mi = 0; mi < 2; mi++) {
                int r = wm * 32 + mi * 16 + g;
                int cc = ks * 8 + tg;
                ah[mi][0] = Ahu[r * 36 + cc];
                ah[mi][1] = Ahu[(r + 8) * 36 + cc];
                ah[mi][2] = Ahu[r * 36 + cc + 4];
                ah[mi][3] = Ahu[(r + 8) * 36 + cc + 4];
                al[mi][0] = Alu[r * 36 + cc];
                al[mi][1] = Alu[(r + 8) * 36 + cc];
                al[mi][2] = Alu[r * 36 + cc + 4];
                al[mi][3] = Alu[(r + 8) * 36 + cc + 4];
            }
#pragma unroll
            for (int ni = 0; ni < 4; ni++) {
                int bn = wn * 32 + ni * 8 + g;
                int bk = ks * 8 + tg;
                uint32_t bh[2] = {Bhu[bn * 36 + bk], Bhu[bn * 36 + bk + 4]};
                uint32_t bl[2] = {Blu[bn * 36 + bk], Blu[bn * 36 + bk + 4]};
#pragma unroll
                for (int mi = 0; mi < 2; mi++) {
                    mma8(acc[mi][ni], ah[mi], bh);
                    mma8(acc[mi][ni], ah[mi], bl);
                    if (sel < 2) mma8(acc[mi][ni], al[mi], bh);
                }
            }
        }
        if (c < 31) {
            __syncthreads();
            store();
            __syncthreads();
        }
    }

#pragma unroll
    for (int mi = 0; mi < 2; mi++) {
        int row = m0 + wm * 32 + mi * 16 + g;
#pragma unroll
        for (int ni = 0; ni < 4; ni++) {
            int col = wn * 32 + ni * 8 + tg * 2;
            *(float2*)&outp[(size_t)row * H_ + col] =
                make_float2(acc[mi][ni][0], acc[mi][ni][1]);
            *(float2*)&outp[(size_t)(row + 8) * H_ + col] =
                make_float2(acc[mi][ni][2], acc[mi][ni][3]);
        }
    }
}

// ---------------------------------------------------------------------------
// Flash attention via mma.sync tf32.
// BQ=64, BK=64. 8 warps (4m x 2n). QK^T 3xTF32; PV single tf32 (rna-rounded).
// ---------------------------------------------------------------------------
#define AQH 0
#define AQL 8448        // 64*132
#define AKH 16896
#define AKL 25344
#define AVS 33792       // V: [64 k][136]
#define APS 42496       // P: [64][68]
#define AMX 46848
#define ASU 46976
#define A_SMEM (47104 * 4)   // 188416 B

__global__ __launch_bounds__(256, 1) void attn_tc(float* __restrict__ out)
{
    extern __shared__ float sm[];
    float* Qh = sm + AQH;  float* Ql = sm + AQL;
    float* Kh = sm + AKH;  float* Kl = sm + AKL;
    float* Vs = sm + AVS;  float* Ps = sm + APS;
    float* smax = sm + AMX;  float* ssum = sm + ASU;
    const uint32_t* Qhu = (const uint32_t*)Qh;
    const uint32_t* Qlu = (const uint32_t*)Ql;
    const uint32_t* Khu = (const uint32_t*)Kh;
    const uint32_t* Klu = (const uint32_t*)Kl;
    const uint32_t* Vsu = (const uint32_t*)Vs;
    const uint32_t* Psu = (const uint32_t*)Ps;

    const int t   = threadIdx.x;
    const int wid = t >> 5, lane = t & 31;
    const int wm  = wid >> 1, wn = wid & 1;
    const int g   = lane >> 2, tg = lane & 3;
    const int qt  = (int)gridDim.x - 1 - (int)blockIdx.x;
    const int b   = blockIdx.y;
    const size_t base = (size_t)b * (T_ * H_);
    const float scale = 45.25483399593904f;   // sqrt(2048)

    // Q: 64x128, scaled + split
#pragma unroll
    for (int p = 0; p < 8; p++) {
        int idx = p * 256 + t;
        int row = idx >> 5, c4 = idx & 31;
        float4 v = *(const float4*)&g_q[base + (size_t)(qt * 64 + row) * H_ + c4 * 4];
        v.x *= scale; v.y *= scale; v.z *= scale; v.w *= scale;
        float4 h = {tf32r(v.x), tf32r(v.y), tf32r(v.z), tf32r(v.w)};
        float4 l = {tf32r(v.x - h.x), tf32r(v.y - h.y),
                    tf32r(v.z - h.z), tf32r(v.w - h.w)};
        *(float4*)&Qh[row * 132 + c4 * 4] = h;
        *(float4*)&Ql[row * 132 + c4 * 4] = l;
    }

    float of[8][4];
#pragma unroll
    for (int ni = 0; ni < 8; ni++)
#pragma unroll
        for (int r = 0; r < 4; r++) of[ni][r] = 0.f;
    float mrun0 = -INFINITY, mrun1 = -INFINITY;
    float lrun0 = 0.f, lrun1 = 0.f;

    const int r0 = wm * 16 + g;
    const int r1 = r0 + 8;
    const int ntiles = qt + 1;

    for (int kt = 0; kt < ntiles; kt++) {
        __syncthreads();
        // K: 64x128 split hi/lo; V: 64x128 tf32-rounded (k-major)
#pragma unroll
        for (int p = 0; p < 8; p++) {
            int idx = p * 256 + t;
            int row = idx >> 5, c4 = idx & 31;
            float4 v = *(const float4*)&g_k[base + (size_t)(kt * 64 + row) * H_ + c4 * 4];
            float4 h = {tf32r(v.x), tf32r(v.y), tf32r(v.z), tf32r(v.w)};
            float4 l = {tf32r(v.x - h.x), tf32r(v.y - h.y),
                        tf32r(v.z - h.z), tf32r(v.w - h.w)};
            *(float4*)&Kh[row * 132 + c4 * 4] = h;
            *(float4*)&Kl[row * 132 + c4 * 4] = l;

            float4 w = *(const float4*)&g_v[base + (size_t)(kt * 64 + row) * H_ + c4 * 4];
            float4 wh = {tf32r(w.x), tf32r(w.y), tf32r(w.z), tf32r(w.w)};
            *(float4*)&Vs[row * 136 + c4 * 4] = wh;
        }
        __syncthreads();

        // S = Q K^T  (64x64), 3xTF32.  Warp covers 16 rows x 32 cols.
        float sfrag[4][4];
#pragma unroll
        for (int ni = 0; ni < 4; ni++)
#pragma unroll
            for (int r = 0; r < 4; r++) sfrag[ni][r] = 0.f;
#pragma unroll 4
        for (int ks = 0; ks < 16; ks++) {
            uint32_t ah[4], al[4];
            int cc = ks * 8 + tg;
            ah[0] = Qhu[r0 * 132 + cc];     ah[1] = Qhu[r1 * 132 + cc];
            ah[2] = Qhu[r0 * 132 + cc + 4]; ah[3] = Qhu[r1 * 132 + cc + 4];
            al[0] = Qlu[r0 * 132 + cc];     al[1] = Qlu[r1 * 132 + cc];
            al[2] = Qlu[r0 * 132 + cc + 4]; al[3] = Qlu[r1 * 132 + cc + 4];
#pragma unroll
            for (int ni = 0; ni < 4; ni++) {
                int bn = wn * 32 + ni * 8 + g;
                uint32_t bh[2] = {Khu[bn * 132 + cc], Khu[bn * 132 + cc + 4]};
                uint32_t bl[2] = {Klu[bn * 132 + cc], Klu[bn * 132 + cc + 4]};
                mma8(sfrag[ni], ah, bh);
                mma8(sfrag[ni], ah, bl);
                mma8(sfrag[ni], al, bh);
            }
        }

        // causal mask: only the diagonal tile (kt == qt)
        if (kt == qt) {
#pragma unroll
            for (int ni = 0; ni < 4; ni++) {
                int col = wn * 32 + ni * 8 + tg * 2;   // local col in [0,64)
                if (col     > r0)     sfrag[ni][0] = -INFINITY;
                if (col + 1 > r0)     sfrag[ni][1] = -INFINITY;
                if (col     > r0 + 8) sfrag[ni][2] = -INFINITY;
                if (col + 1 > r0 + 8) sfrag[ni][3] = -INFINITY;
            }
        }

        // row max across this warp's 32 cols, then across the 2 n-warps
        float pm0 = -INFINITY, pm1 = -INFINITY;
#pragma unroll
        for (int ni = 0; ni < 4; ni++) {
            pm0 = fmaxf(pm0, fmaxf(sfrag[ni][0], sfrag[ni][1]));
            pm1 = fmaxf(pm1, fmaxf(sfrag[ni][2], sfrag[ni][3]));
        }
        pm0 = fmaxf(pm0, __shfl_xor_sync(0xffffffffu, pm0, 1));
        pm0 = fmaxf(pm0, __shfl_xor_sync(0xffffffffu, pm0, 2));
        pm1 = fmaxf(pm1, __shfl_xor_sync(0xffffffffu, pm1, 1));
        pm1 = fmaxf(pm1, __shfl_xor_sync(0xffffffffu, pm1, 2));
        if (tg == 0) { smax[wn * 64 + r0] = pm0; smax[wn * 64 + r1] = pm1; }
        __syncthreads();

        float m0n = fmaxf(mrun0, fmaxf(smax[r0], smax[64 + r0]));
        float m1n = fmaxf(mrun1, fmaxf(smax[r1], smax[64 + r1]));
        float f0 = __expf(mrun0 - m0n);
        float f1 = __expf(mrun1 - m1n);
        mrun0 = m0n; mrun1 = m1n;

        // exp, partial sums, write P (tf32-rounded)
        float ps0 = 0.f, ps1 = 0.f;
#pragma unroll
        for (int ni = 0; ni < 4; ni++) {
            float e0 = __expf(sfrag[ni][0] - m0n);
            float e1 = __expf(sfrag[ni][1] - m0n);
            float e2 = __expf(sfrag[ni][2] - m1n);
            float e3 = __expf(sfrag[ni][3] - m1n);
            ps0 += e0 + e1; ps1 += e2 + e3;
            int col = wn * 32 + ni * 8 + tg * 2;
            *(float2*)&Ps[r0 * 68 + col] = make_float2(tf32r(e0), tf32r(e1));
            *(float2*)&Ps[r1 * 68 + col] = make_float2(tf32r(e2), tf32r(e3));
        }
        ps0 += __shfl_xor_sync(0xffffffffu, ps0, 1);
        ps0 += __shfl_xor_sync(0xffffffffu, ps0, 2);
        ps1 += __shfl_xor_sync(0xffffffffu, ps1, 1);
        ps1 += __shfl_xor_sync(0xffffffffu, ps1, 2);
        if (tg == 0) { ssum[wn * 64 + r0] = ps0; ssum[wn * 64 + r1] = ps1; }

        // rescale O
#pragma unroll
        for (int ni = 0; ni < 8; ni++) {
            of[ni][0] *= f0; of[ni][1] *= f0;
            of[ni][2] *= f1; of[ni][3] *= f1;
        }
        __syncthreads();
        lrun0 = lrun0 * f0 + ssum[r0] + ssum[64 + r0];
        lrun1 = lrun1 * f1 + ssum[r1] + ssum[64 + r1];

        // O += P V  (single tf32); k-dim = 64 keys -> 8 k-steps
#pragma unroll
        for (int ks = 0; ks < 8; ks++) {
            uint32_t pa[4];
            int cc = ks * 8 + tg;
            pa[0] = Psu[r0 * 68 + cc];     pa[1] = Psu[r1 * 68 + cc];
            pa[2] = Psu[r0 * 68 + cc + 4]; pa[3] = Psu[r1 * 68 + cc + 4];
#pragma unroll
            for (int ni = 0; ni < 8; ni++) {
                int bn = wn * 64 + ni * 8 + g;
                uint32_t bv[2] = {Vsu[cc * 136 + bn], Vsu[(cc + 4) * 136 + bn]};
                mma8(of[ni], pa, bv);
            }
        }
    }

    // epilogue
    float inv0 = 1.f / lrun0;
    float inv1 = 1.f / lrun1;
    int grow = qt * 64 + r0;
#pragma unroll
    for (int ni = 0; ni < 8; ni++) {
        int col = wn * 64 + ni * 8 + tg * 2;
        *(float2*)&out[base + (size_t)grow * H_ + col] =
            make_float2(of[ni][0] * inv0, of[ni][1] * inv0);
        *(float2*)&out[base + (size_t)(grow + 8) * H_ + col] =
            make_float2(of[ni][2] * inv1, of[ni][3] * inv1);
    }
}

// ---------------------------------------------------------------------------
extern "C" void kernel_launch(void* const* d_in, const int* in_sizes, int n_in,
                              void* d_out, int out_size)
{
    const float* x  = (const float*)d_in[0];
    const float* Wq = (const float*)d_in[1];
    const float* Wk = (const float*)d_in[2];
    const float* Wv = (const float*)d_in[3];
    float* out = (float*)d_out;

    transpose_w<<<dim3(E_/32, H_/32, 3), 256>>>(Wq, Wk, Wv);

    cudaFuncSetAttribute(proj_tc,
                         cudaFuncAttributeMaxDynamicSharedMemorySize, PJ_SMEM);
    proj_tc<<<dim3(BT_/64, 3), 256, PJ_SMEM>>>(x);

    cudaFuncSetAttribute(attn_tc,
                         cudaFuncAttributeMaxDynamicSharedMemorySize, A_SMEM);
    attn_tc<<<dim3(T_/64, B_), 256, A_SMEM>>>(out);
}

// round 8
// speedup vs baseline: 1.8480x; 1.2648x over previous
#include <cuda_runtime.h>
#include <cuda_fp16.h>
#include <math.h>
#include <cstdint>

#define B_  8
#define T_  2048
#define E_  1024
#define H_  128
#define BT_ (B_*T_)

// scratch (allocation-free: __device__ globals)
__device__ float g_q[BT_*H_];
__device__ float g_k[BT_*H_];
__device__ float g_v[BT_*H_];
__device__ float g_wt[3*H_*E_];   // W^T: [3][128 n][1024 k]

// ---------------------------------------------------------------------------
__device__ __forceinline__ float tf32r(float x) {
    float r; asm("cvt.rna.tf32.f32 %0, %1;" : "=f"(r) : "f"(x)); return r;
}

__device__ __forceinline__ void split2(float x, float y, uint32_t& hi, uint32_t& lo) {
    __half2 h = __floats2half2_rn(x, y);
    float2 f = __half22float2(h);
    __half2 l = __floats2half2_rn(x - f.x, y - f.y);
    hi = *(uint32_t*)&h; lo = *(uint32_t*)&l;
}

__device__ __forceinline__ void mma8(float* d, const uint32_t* a, const uint32_t* b) {
    asm volatile(
        "mma.sync.aligned.m16n8k8.row.col.f32.tf32.tf32.f32 "
        "{%0,%1,%2,%3}, {%4,%5,%6,%7}, {%8,%9}, {%0,%1,%2,%3};"
        : "+f"(d[0]), "+f"(d[1]), "+f"(d[2]), "+f"(d[3])
        : "r"(a[0]), "r"(a[1]), "r"(a[2]), "r"(a[3]), "r"(b[0]), "r"(b[1]));
}

__device__ __forceinline__ void mma16(float* d, const uint32_t* a, const uint32_t* b) {
    asm volatile(
        "mma.sync.aligned.m16n8k16.row.col.f32.f16.f16.f32 "
        "{%0,%1,%2,%3}, {%4,%5,%6,%7}, {%8,%9}, {%0,%1,%2,%3};"
        : "+f"(d[0]), "+f"(d[1]), "+f"(d[2]), "+f"(d[3])
        : "r"(a[0]), "r"(a[1]), "r"(a[2]), "r"(a[3]), "r"(b[0]), "r"(b[1]));
}

// ---------------------------------------------------------------------------
// W transpose: Wt[n][k] = W[k][n]   (1024x128 -> 128x1024), x3 weights
// ---------------------------------------------------------------------------
__global__ void transpose_w(const float* __restrict__ Wq,
                            const float* __restrict__ Wk,
                            const float* __restrict__ Wv)
{
    __shared__ float tile[32][33];
    const int sel = blockIdx.z;
    const float* __restrict__ W = (sel == 0) ? Wq : (sel == 1) ? Wk : Wv;
    float* wt = g_wt + (size_t)sel * H_ * E_;
    const int k0 = blockIdx.x * 32, n0 = blockIdx.y * 32;
    const int tx = threadIdx.x & 31, ty = threadIdx.x >> 5;
#pragma unroll
    for (int i = 0; i < 4; i++)
        tile[ty + 8*i][tx] = W[(size_t)(k0 + ty + 8*i) * H_ + n0 + tx];
    __syncthreads();
#pragma unroll
    for (int i = 0; i < 4; i++)
        wt[(size_t)(n0 + ty + 8*i) * E_ + k0 + tx] = tile[tx][ty + 8*i];
}

// ---------------------------------------------------------------------------
// Projection: out = x @ W  via mma.sync fp16, 2-way split (3 products; 2 for V).
// CTA 64x128, 8 warps (2m x 4n), warp tile 32x32. K chunks of 32.
// LDG->reg prefetch of next chunk overlaps global latency with MMA.
// ---------------------------------------------------------------------------
#define PJS 40                                   // halves per smem row
#define PJ_A1 0
#define PJ_A2 (64*PJS)
#define PJ_B1 (2*64*PJS)
#define PJ_B2 (2*64*PJS + 128*PJS)
#define PJ_SMEM ((2*64*PJS + 2*128*PJS) * 2)     // 30720 B

__global__ __launch_bounds__(256, 2) void proj_tc(const float* __restrict__ x)
{
    extern __shared__ __half sh[];
    const int t    = threadIdx.x;
    const int wid  = t >> 5, lane = t & 31;
    const int wm   = wid >> 2, wn = wid & 3;
    const int g    = lane >> 2, tg = lane & 3;
    const int sel  = blockIdx.y;
    const int m0   = blockIdx.x * 64;

    const float* __restrict__ wt = g_wt + (size_t)sel * (H_ * E_);
    float* outp = (sel == 0) ? g_q : (sel == 1) ? g_k : g_v;

    float acc[2][4][4];
#pragma unroll
    for (int mi = 0; mi < 2; mi++)
#pragma unroll
        for (int ni = 0; ni < 4; ni++)
#pragma unroll
            for (int r = 0; r < 4; r++) acc[mi][ni][r] = 0.f;

    const int ac4 = t & 7;          // float4 col 0..7 within the 32-k chunk
    float4 fa[2], fb[4];

    auto fetch = [&](int c) {
        const int k0 = c * 32;
#pragma unroll
        for (int p = 0; p < 2; p++) {
            int row = (p * 256 + t) >> 3;
            fa[p] = *(const float4*)&x[(size_t)(m0 + row) * E_ + k0 + ac4 * 4];
        }
#pragma unroll
        for (int p = 0; p < 4; p++) {
            int row = (p * 256 + t) >> 3;
            fb[p] = *(const float4*)&wt[(size_t)row * E_ + k0 + ac4 * 4];
        }
    };
    auto store = [&]() {
#pragma unroll
        for (int p = 0; p < 2; p++) {
            int row = (p * 256 + t) >> 3;
            float4 v = fa[p];
            uint32_t h0, l0, h1, l1;
            split2(v.x, v.y, h0, l0);
            split2(v.z, v.w, h1, l1);
            int o = row * PJS + ac4 * 4;
            *(uint32_t*)&sh[PJ_A1 + o]     = h0;
            *(uint32_t*)&sh[PJ_A1 + o + 2] = h1;
            *(uint32_t*)&sh[PJ_A2 + o]     = l0;
            *(uint32_t*)&sh[PJ_A2 + o + 2] = l1;
        }
#pragma unroll
        for (int p = 0; p < 4; p++) {
            int row = (p * 256 + t) >> 3;
            float4 v = fb[p];
            uint32_t h0, l0, h1, l1;
            split2(v.x, v.y, h0, l0);
            split2(v.z, v.w, h1, l1);
            int o = row * PJS + ac4 * 4;
            *(uint32_t*)&sh[PJ_B1 + o]     = h0;
            *(uint32_t*)&sh[PJ_B1 + o + 2] = h1;
            *(uint32_t*)&sh[PJ_B2 + o]     = l0;
            *(uint32_t*)&sh[PJ_B2 + o + 2] = l1;
        }
    };

#define U32S(off) (*(const uint32_t*)&sh[off])

    fetch(0);
    store();
    __syncthreads();

    for (int c = 0; c < 32; c++) {
        if (c < 31) fetch(c + 1);

#pragma unroll
        for (int s = 0; s < 2; s++) {
            uint32_t a1[2][4], a2[2][4];
#pragma unroll
            for (int mi = 0; mi < 2; mi++) {
                int r = wm * 32 + mi * 16 + g;
                int o = r * PJS + s * 16 + 2 * tg;
                a1[mi][0] = U32S(PJ_A1 + o);
                a1[mi][1] = U32S(PJ_A1 + o + 8*PJS);
                a1[mi][2] = U32S(PJ_A1 + o + 8);
                a1[mi][3] = U32S(PJ_A1 + o + 8*PJS + 8);
                a2[mi][0] = U32S(PJ_A2 + o);
                a2[mi][1] = U32S(PJ_A2 + o + 8*PJS);
                a2[mi][2] = U32S(PJ_A2 + o + 8);
                a2[mi][3] = U32S(PJ_A2 + o + 8*PJS + 8);
            }
#pragma unroll
            for (int ni = 0; ni < 4; ni++) {
                int bn = wn * 32 + ni * 8 + g;
                int bo = bn * PJS + s * 16 + 2 * tg;
                uint32_t b1[2] = {U32S(PJ_B1 + bo), U32S(PJ_B1 + bo + 8)};
                uint32_t b2[2] = {U32S(PJ_B2 + bo), U32S(PJ_B2 + bo + 8)};
#pragma unroll
                for (int mi = 0; mi < 2; mi++) {
                    mma16(acc[mi][ni], a1[mi], b1);
                    mma16(acc[mi][ni], a1[mi], b2);
                    if (sel < 2) mma16(acc[mi][ni], a2[mi], b1);
                }
            }
        }
        if (c < 31) {
            __syncthreads();
            store();
            __syncthreads();
        }
    }

#pragma unroll
    for (int mi = 0; mi < 2; mi++) {
        int row = m0 + wm * 32 + mi * 16 + g;
#pragma unroll
        for (int ni = 0; ni < 4; ni++) {
            int col = wn * 32 + ni * 8 + tg * 2;
            *(float2*)&outp[(size_t)row * H_ + col] =
                make_float2(acc[mi][ni][0], acc[mi][ni][1]);
            *(float2*)&outp[(size_t)(row + 8) * H_ + col] =
                make_float2(acc[mi][ni][2], acc[mi][ni][3]);
        }
    }
}

// ---------------------------------------------------------------------------
// Flash attention via mma.sync tf32.
// BQ=64, BK=64. 8 warps (4m x 2n). QK^T 3xTF32; PV single tf32 (rna-rounded).
// Register prefetch of next K/V tile; pair named barriers for softmax exchange.
// ---------------------------------------------------------------------------
#define AQH 0
#define AQL 8448        // 64*132
#define AKH 16896
#define AKL 25344
#define AVS 33792       // V: [64 k][136]
#define APS 42496       // P: [64][68]
#define AMX 46848
#define ASU 46976
#define A_SMEM (47104 * 4)   // 188416 B

__global__ __launch_bounds__(256, 1) void attn_tc(float* __restrict__ out)
{
    extern __shared__ float sm[];
    float* Qh = sm + AQH;  float* Ql = sm + AQL;
    float* Kh = sm + AKH;  float* Kl = sm + AKL;
    float* Vs = sm + AVS;  float* Ps = sm + APS;
    float* smax = sm + AMX;  float* ssum = sm + ASU;
    const uint32_t* Qhu = (const uint32_t*)Qh;
    const uint32_t* Qlu = (const uint32_t*)Ql;
    const uint32_t* Khu = (const uint32_t*)Kh;
    const uint32_t* Klu = (const uint32_t*)Kl;
    const uint32_t* Vsu = (const uint32_t*)Vs;
    const uint32_t* Psu = (const uint32_t*)Ps;

    const int t   = threadIdx.x;
    const int wid = t >> 5, lane = t & 31;
    const int wm  = wid >> 1, wn = wid & 1;
    const int g   = lane >> 2, tg = lane & 3;
    const int qt  = (int)gridDim.x - 1 - (int)blockIdx.x;
    const int b   = blockIdx.y;
    const size_t base = (size_t)b * (T_ * H_);
    const float scale = 45.25483399593904f;   // sqrt(2048)

    // Q: 64x128, scaled + split
#pragma unroll
    for (int p = 0; p < 8; p++) {
        int idx = p * 256 + t;
        int row = idx >> 5, c4 = idx & 31;
        float4 v = *(const float4*)&g_q[base + (size_t)(qt * 64 + row) * H_ + c4 * 4];
        v.x *= scale; v.y *= scale; v.z *= scale; v.w *= scale;
        float4 h = {tf32r(v.x), tf32r(v.y), tf32r(v.z), tf32r(v.w)};
        float4 l = {tf32r(v.x - h.x), tf32r(v.y - h.y),
                    tf32r(v.z - h.z), tf32r(v.w - h.w)};
        *(float4*)&Qh[row * 132 + c4 * 4] = h;
        *(float4*)&Ql[row * 132 + c4 * 4] = l;
    }

    float of[8][4];
#pragma unroll
    for (int ni = 0; ni < 8; ni++)
#pragma unroll
        for (int r = 0; r < 4; r++) of[ni][r] = 0.f;
    float mrun0 = -INFINITY, mrun1 = -INFINITY;
    float lrun0 = 0.f, lrun1 = 0.f;

    const int r0 = wm * 16 + g;
    const int r1 = r0 + 8;
    const int ntiles = qt + 1;
    const int lrow = t >> 5, lc4 = t & 31;   // K/V loader mapping

    float4 pk[8], pv[8];
    auto fetchKV = [&](int kt) {
#pragma unroll
        for (int p = 0; p < 8; p++) {
            int row = p * 8 + lrow;
            pk[p] = *(const float4*)&g_k[base + (size_t)(kt * 64 + row) * H_ + lc4 * 4];
            pv[p] = *(const float4*)&g_v[base + (size_t)(kt * 64 + row) * H_ + lc4 * 4];
        }
    };
    auto storeKV = [&]() {
#pragma unroll
        for (int p = 0; p < 8; p++) {
            int row = p * 8 + lrow;
            float4 v = pk[p];
            float4 h = {tf32r(v.x), tf32r(v.y), tf32r(v.z), tf32r(v.w)};
            float4 l = {tf32r(v.x - h.x), tf32r(v.y - h.y),
                        tf32r(v.z - h.z), tf32r(v.w - h.w)};
            *(float4*)&Kh[row * 132 + lc4 * 4] = h;
            *(float4*)&Kl[row * 132 + lc4 * 4] = l;
            float4 w = pv[p];
            float4 wh = {tf32r(w.x), tf32r(w.y), tf32r(w.z), tf32r(w.w)};
            *(float4*)&Vs[row * 136 + lc4 * 4] = wh;
        }
    };

    fetchKV(0);

    for (int kt = 0; kt < ntiles; kt++) {
        __syncthreads();   // prev PV done reading Vs/Ps; Q store visible
        storeKV();
        __syncthreads();
        if (kt < ntiles - 1) fetchKV(kt + 1);

        // S = Q K^T  (64x64), 3xTF32.  Warp covers 16 rows x 32 cols.
        float sfrag[4][4];
#pragma unroll
        for (int ni = 0; ni < 4; ni++)
#pragma unroll
            for (int r = 0; r < 4; r++) sfrag[ni][r] = 0.f;
#pragma unroll 4
        for (int ks = 0; ks < 16; ks++) {
            uint32_t ah[4], al[4];
            int cc = ks * 8 + tg;
            ah[0] = Qhu[r0 * 132 + cc];     ah[1] = Qhu[r1 * 132 + cc];
            ah[2] = Qhu[r0 * 132 + cc + 4]; ah[3] = Qhu[r1 * 132 + cc + 4];
            al[0] = Qlu[r0 * 132 + cc];     al[1] = Qlu[r1 * 132 + cc];
            al[2] = Qlu[r0 * 132 + cc + 4]; al[3] = Qlu[r1 * 132 + cc + 4];
#pragma unroll
            for (int ni = 0; ni < 4; ni++) {
                int bn = wn * 32 + ni * 8 + g;
                uint32_t bh[2] = {Khu[bn * 132 + cc], Khu[bn * 132 + cc + 4]};
                uint32_t bl[2] = {Klu[bn * 132 + cc], Klu[bn * 132 + cc + 4]};
                mma8(sfrag[ni], ah, bh);
                mma8(sfrag[ni], ah, bl);
                mma8(sfrag[ni], al, bh);
            }
        }

        // causal mask: only the diagonal tile (kt == qt)
        if (kt == qt) {
#pragma unroll
            for (int ni = 0; ni < 4; ni++) {
                int col = wn * 32 + ni * 8 + tg * 2;   // local col in [0,64)
                if (col     > r0)     sfrag[ni][0] = -INFINITY;
                if (col + 1 > r0)     sfrag[ni][1] = -INFINITY;
                if (col     > r0 + 8) sfrag[ni][2] = -INFINITY;
                if (col + 1 > r0 + 8) sfrag[ni][3] = -INFINITY;
            }
        }

        // row max across this warp's 32 cols, then across the 2 n-warps (pair)
        float pm0 = -INFINITY, pm1 = -INFINITY;
#pragma unroll
        for (int ni = 0; ni < 4; ni++) {
            pm0 = fmaxf(pm0, fmaxf(sfrag[ni][0], sfrag[ni][1]));
            pm1 = fmaxf(pm1, fmaxf(sfrag[ni][2], sfrag[ni][3]));
        }
        pm0 = fmaxf(pm0, __shfl_xor_sync(0xffffffffu, pm0, 1));
        pm0 = fmaxf(pm0, __shfl_xor_sync(0xffffffffu, pm0, 2));
        pm1 = fmaxf(pm1, __shfl_xor_sync(0xffffffffu, pm1, 1));
        pm1 = fmaxf(pm1, __shfl_xor_sync(0xffffffffu, pm1, 2));
        if (tg == 0) { smax[wn * 64 + r0] = pm0; smax[wn * 64 + r1] = pm1; }
        asm volatile("bar.sync %0, 64;" :: "r"(1 + wm) : "memory");

        float m0n = fmaxf(mrun0, fmaxf(smax[r0], smax[64 + r0]));
        float m1n = fmaxf(mrun1, fmaxf(smax[r1], smax[64 + r1]));
        float f0 = __expf(mrun0 - m0n);
        float f1 = __expf(mrun1 - m1n);
        mrun0 = m0n; mrun1 = m1n;

        // exp, partial sums, write P (tf32-rounded)
        float ps0 = 0.f, ps1 = 0.f;
#pragma unroll
        for (int ni = 0; ni < 4; ni++) {
            float e0 = __expf(sfrag[ni][0] - m0n);
            float e1 = __expf(sfrag[ni][1] - m0n);
            float e2 = __expf(sfrag[ni][2] - m1n);
            float e3 = __expf(sfrag[ni][3] - m1n);
            ps0 += e0 + e1; ps1 += e2 + e3;
            int col = wn * 32 + ni * 8 + tg * 2;
            *(float2*)&Ps[r0 * 68 + col] = make_float2(tf32r(e0), tf32r(e1));
            *(float2*)&Ps[r1 * 68 + col] = make_float2(tf32r(e2), tf32r(e3));
        }
        ps0 += __shfl_xor_sync(0xffffffffu, ps0, 1);
        ps0 += __shfl_xor_sync(0xffffffffu, ps0, 2);
        ps1 += __shfl_xor_sync(0xffffffffu, ps1, 1);
        ps1 += __shfl_xor_sync(0xffffffffu, ps1, 2);
        if (tg == 0) { ssum[wn * 64 + r0] = ps0; ssum[wn * 64 + r1] = ps1; }

        // rescale O while the pair barrier drains
#pragma unroll
        for (int ni = 0; ni < 8; ni++) {
            of[ni][0] *= f0; of[ni][1] *= f0;
            of[ni][2] *= f1; of[ni][3] *= f1;
        }
        asm volatile("bar.sync %0, 64;" :: "r"(1 + wm) : "memory");
        lrun0 = lrun0 * f0 + ssum[r0] + ssum[64 + r0];
        lrun1 = lrun1 * f1 + ssum[r1] + ssum[64 + r1];

        // O += P V  (single tf32); k-dim = 64 keys -> 8 k-steps
#pragma unroll
        for (int ks = 0; ks < 8; ks++) {
            uint32_t pa[4];
            int cc = ks * 8 + tg;
            pa[0] = Psu[r0 * 68 + cc];     pa[1] = Psu[r1 * 68 + cc];
            pa[2] = Psu[r0 * 68 + cc + 4]; pa[3] = Psu[r1 * 68 + cc + 4];
#pragma unroll
            for (int ni = 0; ni < 8; ni++) {
                int bn = wn * 64 + ni * 8 + g;
                uint32_t bv[2] = {Vsu[cc * 136 + bn], Vsu[(cc + 4) * 136 + bn]};
                mma8(of[ni], pa, bv);
            }
        }
    }

    // epilogue
    float inv0 = 1.f / lrun0;
    float inv1 = 1.f / lrun1;
    int grow = qt * 64 + r0;
#pragma unroll
    for (int ni = 0; ni < 8; ni++) {
        int col = wn * 64 + ni * 8 + tg * 2;
        *(float2*)&out[base + (size_t)grow * H_ + col] =
            make_float2(of[ni][0] * inv0, of[ni][1] * inv0);
        *(float2*)&out[base + (size_t)(grow + 8) * H_ + col] =
            make_float2(of[ni][2] * inv1, of[ni][3] * inv1);
    }
}

// ---------------------------------------------------------------------------
extern "C" void kernel_launch(void* const* d_in, const int* in_sizes, int n_in,
                              void* d_out, int out_size)
{
    const float* x  = (const float*)d_in[0];
    const float* Wq = (const float*)d_in[1];
    const float* Wk = (const float*)d_in[2];
    const float* Wv = (const float*)d_in[3];
    float* out = (float*)d_out;

    transpose_w<<<dim3(E_/32, H_/32, 3), 256>>>(Wq, Wk, Wv);

    cudaFuncSetAttribute(proj_tc,
                         cudaFuncAttributeMaxDynamicSharedMemorySize, PJ_SMEM);
    proj_tc<<<dim3(BT_/64, 3), 256, PJ_SMEM>>>(x);

    cudaFuncSetAttribute(attn_tc,
                         cudaFuncAttributeMaxDynamicSharedMemorySize, A_SMEM);
    attn_tc<<<dim3(T_/64, B_), 256, A_SMEM>>>(out);
}

// round 9
// speedup vs baseline: 2.1648x; 1.1714x over previous
#include <cuda_runtime.h>
#include <cuda_fp16.h>
#include <math.h>
#include <cstdint>

#define B_  8
#define T_  2048
#define E_  1024
#define H_  128
#define BT_ (B_*T_)

// scratch (allocation-free: __device__ globals)
__device__ float g_q[BT_*H_];
__device__ float g_k[BT_*H_];
__device__ float g_v[BT_*H_];
__device__ __half g_w1[3*H_*E_], g_w2[3*H_*E_];   // W^T split: [3][128 n][1024 k]

// ---------------------------------------------------------------------------
__device__ __forceinline__ float tf32r(float x) {
    float r; asm("cvt.rna.tf32.f32 %0, %1;" : "=f"(r) : "f"(x)); return r;
}

__device__ __forceinline__ void split2(float x, float y, uint32_t& hi, uint32_t& lo) {
    __half2 h = __floats2half2_rn(x, y);
    float2 f = __half22float2(h);
    __half2 l = __floats2half2_rn(x - f.x, y - f.y);
    hi = *(uint32_t*)&h; lo = *(uint32_t*)&l;
}

__device__ __forceinline__ void mma8(float* d, const uint32_t* a, const uint32_t* b) {
    asm volatile(
        "mma.sync.aligned.m16n8k8.row.col.f32.tf32.tf32.f32 "
        "{%0,%1,%2,%3}, {%4,%5,%6,%7}, {%8,%9}, {%0,%1,%2,%3};"
        : "+f"(d[0]), "+f"(d[1]), "+f"(d[2]), "+f"(d[3])
        : "r"(a[0]), "r"(a[1]), "r"(a[2]), "r"(a[3]), "r"(b[0]), "r"(b[1]));
}

__device__ __forceinline__ void mma16(float* d, const uint32_t* a, const uint32_t* b) {
    asm volatile(
        "mma.sync.aligned.m16n8k16.row.col.f32.f16.f16.f32 "
        "{%0,%1,%2,%3}, {%4,%5,%6,%7}, {%8,%9}, {%0,%1,%2,%3};"
        : "+f"(d[0]), "+f"(d[1]), "+f"(d[2]), "+f"(d[3])
        : "r"(a[0]), "r"(a[1]), "r"(a[2]), "r"(a[3]), "r"(b[0]), "r"(b[1]));
}

// ---------------------------------------------------------------------------
// W -> W^T, split to fp16 halves.  grid (E/32, H/32, 3), 256 thr
// ---------------------------------------------------------------------------
__global__ void prep_w(const float* __restrict__ Wq,
                       const float* __restrict__ Wk,
                       const float* __restrict__ Wv)
{
    __shared__ float tile[32][33];
    const int sel = blockIdx.z;
    const float* __restrict__ W = (sel == 0) ? Wq : (sel == 1) ? Wk : Wv;
    const int k0 = blockIdx.x * 32, n0 = blockIdx.y * 32;
    const int tx = threadIdx.x & 31, ty = threadIdx.x >> 5;
#pragma unroll
    for (int i = 0; i < 4; i++)
        tile[ty + 8*i][tx] = W[(size_t)(k0 + ty + 8*i) * H_ + n0 + tx];
    __syncthreads();
    uint32_t* w1 = (uint32_t*)g_w1;
    uint32_t* w2 = (uint32_t*)g_w2;
#pragma unroll
    for (int r = 0; r < 2; r++) {
        int slot = r * 256 + threadIdx.x;
        int ni = slot >> 4, kp = slot & 15;
        float a = tile[2*kp][ni], b = tile[2*kp + 1][ni];
        uint32_t h, l;
        split2(a, b, h, l);
        size_t o = ((size_t)(sel * H_ + n0 + ni) * E_ + k0 + 2*kp) >> 1;
        w1[o] = h; w2[o] = l;
    }
}

// ---------------------------------------------------------------------------
// Projection: out = x @ W  via mma.sync fp16, 2-way split (3 products; 2 for V).
// CTA 64x128, 8 warps (2m x 4n), warp tile 32x32. K chunks of 32.
// W pre-split in gmem; x split in-kernel. LDG->reg prefetch per chunk.
// ---------------------------------------------------------------------------
#define PJS 40                                   // halves per smem row
#define PJ_A1 0
#define PJ_A2 (64*PJS)
#define PJ_B1 (2*64*PJS)
#define PJ_B2 (2*64*PJS + 128*PJS)
#define PJ_SMEM ((2*64*PJS + 2*128*PJS) * 2)     // 30720 B

__global__ __launch_bounds__(256, 2) void proj_tc(const float* __restrict__ x)
{
    extern __shared__ __half sh[];
    const int t    = threadIdx.x;
    const int wid  = t >> 5, lane = t & 31;
    const int wm   = wid >> 2, wn = wid & 3;
    const int g    = lane >> 2, tg = lane & 3;
    const int sel  = blockIdx.y;
    const int m0   = blockIdx.x * 64;

    const uint4* __restrict__ ws1 = (const uint4*)(g_w1 + (size_t)sel * H_ * E_);
    const uint4* __restrict__ ws2 = (const uint4*)(g_w2 + (size_t)sel * H_ * E_);
    float* outp = (sel == 0) ? g_q : (sel == 1) ? g_k : g_v;

    float acc[2][4][4];
#pragma unroll
    for (int mi = 0; mi < 2; mi++)
#pragma unroll
        for (int ni = 0; ni < 4; ni++)
#pragma unroll
            for (int r = 0; r < 4; r++) acc[mi][ni][r] = 0.f;

    const int ac4 = t & 7;          // A: float4 col 0..7 in the 32-k chunk
    const int bc8 = t & 3;          // B: uint4 (8 halves) col 0..3
    float4 fa[2];
    uint4  pw1[2], pw2[2];

    auto fetch = [&](int c) {
        const int k0 = c * 32;
#pragma unroll
        for (int p = 0; p < 2; p++) {
            int row = (p * 256 + t) >> 3;
            fa[p] = *(const float4*)&x[(size_t)(m0 + row) * E_ + k0 + ac4 * 4];
        }
#pragma unroll
        for (int p = 0; p < 2; p++) {
            int row = (p * 256 + t) >> 2;
            size_t off = ((size_t)row * E_ + k0) / 8 + bc8;
            pw1[p] = ws1[off];
            pw2[p] = ws2[off];
        }
    };
    auto store = [&]() {
#pragma unroll
        for (int p = 0; p < 2; p++) {
            int row = (p * 256 + t) >> 3;
            float4 v = fa[p];
            uint32_t h0, l0, h1, l1;
            split2(v.x, v.y, h0, l0);
            split2(v.z, v.w, h1, l1);
            int o = row * PJS + ac4 * 4;
            *(uint32_t*)&sh[PJ_A1 + o]     = h0;
            *(uint32_t*)&sh[PJ_A1 + o + 2] = h1;
            *(uint32_t*)&sh[PJ_A2 + o]     = l0;
            *(uint32_t*)&sh[PJ_A2 + o + 2] = l1;
        }
#pragma unroll
        for (int p = 0; p < 2; p++) {
            int row = (p * 256 + t) >> 2;
            int o = row * PJS + bc8 * 8;
            *(uint4*)&sh[PJ_B1 + o] = pw1[p];
            *(uint4*)&sh[PJ_B2 + o] = pw2[p];
        }
    };

#define U32S(off) (*(const uint32_t*)&sh[off])

    fetch(0);
    store();
    __syncthreads();

    for (int c = 0; c < 32; c++) {
        if (c < 31) fetch(c + 1);

#pragma unroll
        for (int s = 0; s < 2; s++) {
            uint32_t a1[2][4], a2[2][4];
#pragma unroll
            for (int mi = 0; mi < 2; mi++) {
                int r = wm * 32 + mi * 16 + g;
                int o = r * PJS + s * 16 + 2 * tg;
                a1[mi][0] = U32S(PJ_A1 + o);
                a1[mi][1] = U32S(PJ_A1 + o + 8*PJS);
                a1[mi][2] = U32S(PJ_A1 + o + 8);
                a1[mi][3] = U32S(PJ_A1 + o + 8*PJS + 8);
                a2[mi][0] = U32S(PJ_A2 + o);
                a2[mi][1] = U32S(PJ_A2 + o + 8*PJS);
                a2[mi][2] = U32S(PJ_A2 + o + 8);
                a2[mi][3] = U32S(PJ_A2 + o + 8*PJS + 8);
            }
#pragma unroll
            for (int ni = 0; ni < 4; ni++) {
                int bn = wn * 32 + ni * 8 + g;
                int bo = bn * PJS + s * 16 + 2 * tg;
                uint32_t b1[2] = {U32S(PJ_B1 + bo), U32S(PJ_B1 + bo + 8)};
                uint32_t b2[2] = {U32S(PJ_B2 + bo), U32S(PJ_B2 + bo + 8)};
#pragma unroll
                for (int mi = 0; mi < 2; mi++) {
                    mma16(acc[mi][ni], a1[mi], b1);
                    mma16(acc[mi][ni], a1[mi], b2);
                    if (sel < 2) mma16(acc[mi][ni], a2[mi], b1);
                }
            }
        }
        if (c < 31) {
            __syncthreads();
            store();
            __syncthreads();
        }
    }

#pragma unroll
    for (int mi = 0; mi < 2; mi++) {
        int row = m0 + wm * 32 + mi * 16 + g;
#pragma unroll
        for (int ni = 0; ni < 4; ni++) {
            int col = wn * 32 + ni * 8 + tg * 2;
            *(float2*)&outp[(size_t)row * H_ + col] =
                make_float2(acc[mi][ni][0], acc[mi][ni][1]);
            *(float2*)&outp[(size_t)(row + 8) * H_ + col] =
                make_float2(acc[mi][ni][2], acc[mi][ni][3]);
        }
    }
}

// ---------------------------------------------------------------------------
// Flash attention. BQ=64, BK=64. 8 warps (4m x 2n).
// QK^T: fp16 split-2, 3 products (mma16).  PV: single tf32 (mma8).
// Register prefetch of next K/V tile; pair named barriers for softmax.
// ---------------------------------------------------------------------------
#define QH1 0
#define QH2 (64*136)        // half indices
#define KH1 (2*64*136)
#define KH2 (3*64*136)
#define HV_END (4*64*136)   // 34816 halves = 69632 B
// float region after halves: Vs[64][136], Ps[64][68], smax[128], ssum[128]
#define A_SMEM (HV_END*2 + (64*136 + 64*68 + 256)*4)   // 122880 B

__global__ __launch_bounds__(256, 1) void attn_tc(float* __restrict__ out)
{
    extern __shared__ __half sh2[];
    __half* shh = sh2;
    float* fbase = (float*)(sh2 + HV_END);
    float* Vs   = fbase;                 // [64][136]
    float* Ps   = Vs + 64*136;           // [64][68]
    float* smax = Ps + 64*68;
    float* ssum = smax + 128;
    const uint32_t* Vsu = (const uint32_t*)Vs;
    const uint32_t* Psu = (const uint32_t*)Ps;

#define HU(off) (*(const uint32_t*)&shh[off])

    const int t   = threadIdx.x;
    const int wid = t >> 5, lane = t & 31;
    const int wm  = wid >> 1, wn = wid & 1;
    const int g   = lane >> 2, tg = lane & 3;
    const int qt  = (int)gridDim.x - 1 - (int)blockIdx.x;
    const int b   = blockIdx.y;
    const size_t base = (size_t)b * (T_ * H_);
    const float scale = 45.25483399593904f;   // sqrt(2048)

    // Q: 64x128, scaled + fp16 split
#pragma unroll
    for (int p = 0; p < 8; p++) {
        int idx = p * 256 + t;
        int row = idx >> 5, c4 = idx & 31;
        float4 v = *(const float4*)&g_q[base + (size_t)(qt * 64 + row) * H_ + c4 * 4];
        v.x *= scale; v.y *= scale; v.z *= scale; v.w *= scale;
        uint32_t h0, l0, h1, l1;
        split2(v.x, v.y, h0, l0);
        split2(v.z, v.w, h1, l1);
        int o = row * 136 + c4 * 4;
        *(uint32_t*)&shh[QH1 + o]     = h0;
        *(uint32_t*)&shh[QH1 + o + 2] = h1;
        *(uint32_t*)&shh[QH2 + o]     = l0;
        *(uint32_t*)&shh[QH2 + o + 2] = l1;
    }

    float of[8][4];
#pragma unroll
    for (int ni = 0; ni < 8; ni++)
#pragma unroll
        for (int r = 0; r < 4; r++) of[ni][r] = 0.f;
    float mrun0 = -INFINITY, mrun1 = -INFINITY;
    float lrun0 = 0.f, lrun1 = 0.f;

    const int r0 = wm * 16 + g;
    const int r1 = r0 + 8;
    const int ntiles = qt + 1;
    const int lrow = t >> 5, lc4 = t & 31;   // K/V loader mapping

    float4 pk[8], pv[8];
    auto fetchKV = [&](int kt) {
#pragma unroll
        for (int p = 0; p < 8; p++) {
            int row = p * 8 + lrow;
            pk[p] = *(const float4*)&g_k[base + (size_t)(kt * 64 + row) * H_ + lc4 * 4];
            pv[p] = *(const float4*)&g_v[base + (size_t)(kt * 64 + row) * H_ + lc4 * 4];
        }
    };
    auto storeKV = [&]() {
#pragma unroll
        for (int p = 0; p < 8; p++) {
            int row = p * 8 + lrow;
            float4 v = pk[p];
            uint32_t h0, l0, h1, l1;
            split2(v.x, v.y, h0, l0);
            split2(v.z, v.w, h1, l1);
            int o = row * 136 + lc4 * 4;
            *(uint32_t*)&shh[KH1 + o]     = h0;
            *(uint32_t*)&shh[KH1 + o + 2] = h1;
            *(uint32_t*)&shh[KH2 + o]     = l0;
            *(uint32_t*)&shh[KH2 + o + 2] = l1;
            float4 w = pv[p];
            float4 wh = {tf32r(w.x), tf32r(w.y), tf32r(w.z), tf32r(w.w)};
            *(float4*)&Vs[row * 136 + lc4 * 4] = wh;
        }
    };

    fetchKV(0);

    for (int kt = 0; kt < ntiles; kt++) {
        __syncthreads();   // prev PV done reading Vs/Ps; Q store visible
        storeKV();
        __syncthreads();
        if (kt < ntiles - 1) fetchKV(kt + 1);

        // S = Q K^T  (64x64), fp16 split-2, 3 products.
        float sfrag[4][4];
#pragma unroll
        for (int ni = 0; ni < 4; ni++)
#pragma unroll
            for (int r = 0; r < 4; r++) sfrag[ni][r] = 0.f;
#pragma unroll
        for (int ks = 0; ks < 8; ks++) {
            uint32_t a1[4], a2[4];
            int cc = ks * 16 + 2 * tg;
            a1[0] = HU(QH1 + r0 * 136 + cc);     a1[1] = HU(QH1 + r1 * 136 + cc);
            a1[2] = HU(QH1 + r0 * 136 + cc + 8); a1[3] = HU(QH1 + r1 * 136 + cc + 8);
            a2[0] = HU(QH2 + r0 * 136 + cc);     a2[1] = HU(QH2 + r1 * 136 + cc);
            a2[2] = HU(QH2 + r0 * 136 + cc + 8); a2[3] = HU(QH2 + r1 * 136 + cc + 8);
#pragma unroll
            for (int ni = 0; ni < 4; ni++) {
                int bn = wn * 32 + ni * 8 + g;
                uint32_t b1[2] = {HU(KH1 + bn * 136 + cc), HU(KH1 + bn * 136 + cc + 8)};
                uint32_t b2[2] = {HU(KH2 + bn * 136 + cc), HU(KH2 + bn * 136 + cc + 8)};
                mma16(sfrag[ni], a1, b1);
                mma16(sfrag[ni], a1, b2);
                mma16(sfrag[ni], a2, b1);
            }
        }

        // causal mask: only the diagonal tile (kt == qt)
        if (kt == qt) {
#pragma unroll
            for (int ni = 0; ni < 4; ni++) {
                int col = wn * 32 + ni * 8 + tg * 2;   // local col in [0,64)
                if (col     > r0)     sfrag[ni][0] = -INFINITY;
                if (col + 1 > r0)     sfrag[ni][1] = -INFINITY;
                if (col     > r0 + 8) sfrag[ni][2] = -INFINITY;
                if (col + 1 > r0 + 8) sfrag[ni][3] = -INFINITY;
            }
        }

        // row max across this warp's 32 cols, then across the 2 n-warps (pair)
        float pm0 = -INFINITY, pm1 = -INFINITY;
#pragma unroll
        for (int ni = 0; ni < 4; ni++) {
            pm0 = fmaxf(pm0, fmaxf(sfrag[ni][0], sfrag[ni][1]));
            pm1 = fmaxf(pm1, fmaxf(sfrag[ni][2], sfrag[ni][3]));
        }
        pm0 = fmaxf(pm0, __shfl_xor_sync(0xffffffffu, pm0, 1));
        pm0 = fmaxf(pm0, __shfl_xor_sync(0xffffffffu, pm0, 2));
        pm1 = fmaxf(pm1, __shfl_xor_sync(0xffffffffu, pm1, 1));
        pm1 = fmaxf(pm1, __shfl_xor_sync(0xffffffffu, pm1, 2));
        if (tg == 0) { smax[wn * 64 + r0] = pm0; smax[wn * 64 + r1] = pm1; }
        asm volatile("bar.sync %0, 64;" :: "r"(1 + wm) : "memory");

        float m0n = fmaxf(mrun0, fmaxf(smax[r0], smax[64 + r0]));
        float m1n = fmaxf(mrun1, fmaxf(smax[r1], smax[64 + r1]));
        float f0 = __expf(mrun0 - m0n);
        float f1 = __expf(mrun1 - m1n);
        mrun0 = m0n; mrun1 = m1n;

        // exp, partial sums, write P (tf32-rounded)
        float ps0 = 0.f, ps1 = 0.f;
#pragma unroll
        for (int ni = 0; ni < 4; ni++) {
            float e0 = __expf(sfrag[ni][0] - m0n);
            float e1 = __expf(sfrag[ni][1] - m0n);
            float e2 = __expf(sfrag[ni][2] - m1n);
            float e3 = __expf(sfrag[ni][3] - m1n);
            ps0 += e0 + e1; ps1 += e2 + e3;
            int col = wn * 32 + ni * 8 + tg * 2;
            *(float2*)&Ps[r0 * 68 + col] = make_float2(tf32r(e0), tf32r(e1));
            *(float2*)&Ps[r1 * 68 + col] = make_float2(tf32r(e2), tf32r(e3));
        }
        ps0 += __shfl_xor_sync(0xffffffffu, ps0, 1);
        ps0 += __shfl_xor_sync(0xffffffffu, ps0, 2);
        ps1 += __shfl_xor_sync(0xffffffffu, ps1, 1);
        ps1 += __shfl_xor_sync(0xffffffffu, ps1, 2);
        if (tg == 0) { ssum[wn * 64 + r0] = ps0; ssum[wn * 64 + r1] = ps1; }

        // rescale O while the pair barrier drains
#pragma unroll
        for (int ni = 0; ni < 8; ni++) {
            of[ni][0] *= f0; of[ni][1] *= f0;
            of[ni][2] *= f1; of[ni][3] *= f1;
        }
        asm volatile("bar.sync %0, 64;" :: "r"(1 + wm) : "memory");
        lrun0 = lrun0 * f0 + ssum[r0] + ssum[64 + r0];
        lrun1 = lrun1 * f1 + ssum[r1] + ssum[64 + r1];

        // O += P V  (single tf32); k-dim = 64 keys -> 8 k-steps
#pragma unroll
        for (int ks = 0; ks < 8; ks++) {
            uint32_t pa[4];
            int cc = ks * 8 + tg;
            pa[0] = Psu[r0 * 68 + cc];     pa[1] = Psu[r1 * 68 + cc];
            pa[2] = Psu[r0 * 68 + cc + 4]; pa[3] = Psu[r1 * 68 + cc + 4];
#pragma unroll
            for (int ni = 0; ni < 8; ni++) {
                int bn = wn * 64 + ni * 8 + g;
                uint32_t bv[2] = {Vsu[cc * 136 + bn], Vsu[(cc + 4) * 136 + bn]};
                mma8(of[ni], pa, bv);
            }
        }
    }

    // epilogue
    float inv0 = 1.f / lrun0;
    float inv1 = 1.f / lrun1;
    int grow = qt * 64 + r0;
#pragma unroll
    for (int ni = 0; ni < 8; ni++) {
        int col = wn * 64 + ni * 8 + tg * 2;
        *(float2*)&out[base + (size_t)grow * H_ + col] =
            make_float2(of[ni][0] * inv0, of[ni][1] * inv0);
        *(float2*)&out[base + (size_t)(grow + 8) * H_ + col] =
            make_float2(of[ni][2] * inv1, of[ni][3] * inv1);
    }
}

// ---------------------------------------------------------------------------
extern "C" void kernel_launch(void* const* d_in, const int* in_sizes, int n_in,
                              void* d_out, int out_size)
{
    const float* x  = (const float*)d_in[0];
    const float* Wq = (const float*)d_in[1];
    const float* Wk = (const float*)d_in[2];
    const float* Wv = (const float*)d_in[3];
    float* out = (float*)d_out;

    prep_w<<<dim3(E_/32, H_/32, 3), 256>>>(Wq, Wk, Wv);

    cudaFuncSetAttribute(proj_tc,
                         cudaFuncAttributeMaxDynamicSharedMemorySize, PJ_SMEM);
    proj_tc<<<dim3(BT_/64, 3), 256, PJ_SMEM>>>(x);

    cudaFuncSetAttribute(attn_tc,
                         cudaFuncAttributeMaxDynamicSharedMemorySize, A_SMEM);
    attn_tc<<<dim3(T_/64, B_), 256, A_SMEM>>>(out);
}

// round 11
// speedup vs baseline: 2.4120x; 1.1142x over previous
#include <cuda_runtime.h>
#include <cuda_fp16.h>
#include <math.h>
#include <cstdint>

#define B_  8
#define T_  2048
#define E_  1024
#define H_  128
#define BT_ (B_*T_)

// scratch (allocation-free: __device__ globals)
__device__ float g_q[BT_*H_];
__device__ float g_k[BT_*H_];
__device__ float g_v[BT_*H_];
__device__ __half g_w1[3*H_*E_], g_w2[3*H_*E_];   // W^T split: [3][128 n][1024 k]

// ---------------------------------------------------------------------------
__device__ __forceinline__ uint32_t smem_u32(const void* p) {
    uint32_t a;
    asm("{ .reg .u64 t; cvta.to.shared.u64 t, %1; cvt.u32.u64 %0, t; }"
        : "=r"(a) : "l"(p));
    return a;
}

__device__ __forceinline__ void split2(float x, float y, uint32_t& hi, uint32_t& lo) {
    __half2 h = __floats2half2_rn(x, y);
    float2 f = __half22float2(h);
    __half2 l = __floats2half2_rn(x - f.x, y - f.y);
    hi = *(uint32_t*)&h; lo = *(uint32_t*)&l;
}

__device__ __forceinline__ void mma16(float* d, const uint32_t* a, const uint32_t* b) {
    asm volatile(
        "mma.sync.aligned.m16n8k16.row.col.f32.f16.f16.f32 "
        "{%0,%1,%2,%3}, {%4,%5,%6,%7}, {%8,%9}, {%0,%1,%2,%3};"
        : "+f"(d[0]), "+f"(d[1]), "+f"(d[2]), "+f"(d[3])
        : "r"(a[0]), "r"(a[1]), "r"(a[2]), "r"(a[3]), "r"(b[0]), "r"(b[1]));
}

__device__ __forceinline__ void ldsm4(uint32_t* r, uint32_t addr) {
    asm volatile("ldmatrix.sync.aligned.m8n8.x4.shared.b16 {%0,%1,%2,%3}, [%4];"
        : "=r"(r[0]), "=r"(r[1]), "=r"(r[2]), "=r"(r[3]) : "r"(addr));
}
__device__ __forceinline__ void ldsm4t(uint32_t* r, uint32_t addr) {
    asm volatile("ldmatrix.sync.aligned.m8n8.x4.trans.shared.b16 {%0,%1,%2,%3}, [%4];"
        : "=r"(r[0]), "=r"(r[1]), "=r"(r[2]), "=r"(r[3]) : "r"(addr));
}

// ---------------------------------------------------------------------------
// W -> W^T, split to fp16 halves.  grid (E/32, H/32, 3), 256 thr
// ---------------------------------------------------------------------------
__global__ void prep_w(const float* __restrict__ Wq,
                       const float* __restrict__ Wk,
                       const float* __restrict__ Wv)
{
    __shared__ float tile[32][33];
    const int sel = blockIdx.z;
    const float* __restrict__ W = (sel == 0) ? Wq : (sel == 1) ? Wk : Wv;
    const int k0 = blockIdx.x * 32, n0 = blockIdx.y * 32;
    const int tx = threadIdx.x & 31, ty = threadIdx.x >> 5;
#pragma unroll
    for (int i = 0; i < 4; i++)
        tile[ty + 8*i][tx] = W[(size_t)(k0 + ty + 8*i) * H_ + n0 + tx];
    __syncthreads();
    uint32_t* w1 = (uint32_t*)g_w1;
    uint32_t* w2 = (uint32_t*)g_w2;
#pragma unroll
    for (int r = 0; r < 2; r++) {
        int slot = r * 256 + threadIdx.x;
        int ni = slot >> 4, kp = slot & 15;
        float a = tile[2*kp][ni], b = tile[2*kp + 1][ni];
        uint32_t h, l;
        split2(a, b, h, l);
        size_t o = ((size_t)(sel * H_ + n0 + ni) * E_ + k0 + 2*kp) >> 1;
        w1[o] = h; w2[o] = l;
    }
}

// ---------------------------------------------------------------------------
// Projection: out = x @ W  via mma.sync fp16, 2-way split (3 products; 2 for V).
// CTA 64x128, 8 warps (2m x 4n), warp tile 32x32. K chunks of 32.
// W pre-split in gmem; x split in-kernel. LDG->reg prefetch per chunk.
// ---------------------------------------------------------------------------
#define PJS 40                                   // halves per smem row
#define PJ_A1 0
#define PJ_A2 (64*PJS)
#define PJ_B1 (2*64*PJS)
#define PJ_B2 (2*64*PJS + 128*PJS)
#define PJ_SMEM ((2*64*PJS + 2*128*PJS) * 2)     // 30720 B

__global__ __launch_bounds__(256, 2) void proj_tc(const float* __restrict__ x)
{
    extern __shared__ __half sh[];
    const int t    = threadIdx.x;
    const int wid  = t >> 5, lane = t & 31;
    const int wm   = wid >> 2, wn = wid & 3;
    const int g    = lane >> 2, tg = lane & 3;
    const int sel  = blockIdx.y;
    const int m0   = blockIdx.x * 64;

    const uint4* __restrict__ ws1 = (const uint4*)(g_w1 + (size_t)sel * H_ * E_);
    const uint4* __restrict__ ws2 = (const uint4*)(g_w2 + (size_t)sel * H_ * E_);
    float* outp = (sel == 0) ? g_q : (sel == 1) ? g_k : g_v;

    float acc[2][4][4];
#pragma unroll
    for (int mi = 0; mi < 2; mi++)
#pragma unroll
        for (int ni = 0; ni < 4; ni++)
#pragma unroll
            for (int r = 0; r < 4; r++) acc[mi][ni][r] = 0.f;

    const int ac4 = t & 7;          // A: float4 col 0..7 in the 32-k chunk
    const int bc8 = t & 3;          // B: uint4 (8 halves) col 0..3
    float4 fa[2];
    uint4  pw1[2], pw2[2];

    auto fetch = [&](int c) {
        const int k0 = c * 32;
#pragma unroll
        for (int p = 0; p < 2; p++) {
            int row = (p * 256 + t) >> 3;
            fa[p] = *(const float4*)&x[(size_t)(m0 + row) * E_ + k0 + ac4 * 4];
        }
#pragma unroll
        for (int p = 0; p < 2; p++) {
            int row = (p * 256 + t) >> 2;
            size_t off = ((size_t)row * E_ + k0) / 8 + bc8;
            pw1[p] = ws1[off];
            pw2[p] = ws2[off];
        }
    };
    auto store = [&]() {
#pragma unroll
        for (int p = 0; p < 2; p++) {
            int row = (p * 256 + t) >> 3;
            float4 v = fa[p];
            uint32_t h0, l0, h1, l1;
            split2(v.x, v.y, h0, l0);
            split2(v.z, v.w, h1, l1);
            int o = row * PJS + ac4 * 4;
            *(uint32_t*)&sh[PJ_A1 + o]     = h0;
            *(uint32_t*)&sh[PJ_A1 + o + 2] = h1;
            *(uint32_t*)&sh[PJ_A2 + o]     = l0;
            *(uint32_t*)&sh[PJ_A2 + o + 2] = l1;
        }
#pragma unroll
        for (int p = 0; p < 2; p++) {
            int row = (p * 256 + t) >> 2;
            int o = row * PJS + bc8 * 8;
            *(uint4*)&sh[PJ_B1 + o] = pw1[p];
            *(uint4*)&sh[PJ_B2 + o] = pw2[p];
        }
    };

#define U32S(off) (*(const uint32_t*)&sh[off])

    fetch(0);
    store();
    __syncthreads();

    for (int c = 0; c < 32; c++) {
        if (c < 31) fetch(c + 1);

#pragma unroll
        for (int s = 0; s < 2; s++) {
            uint32_t a1[2][4], a2[2][4];
#pragma unroll
            for (int mi = 0; mi < 2; mi++) {
                int r = wm * 32 + mi * 16 + g;
                int o = r * PJS + s * 16 + 2 * tg;
                a1[mi][0] = U32S(PJ_A1 + o);
                a1[mi][1] = U32S(PJ_A1 + o + 8*PJS);
                a1[mi][2] = U32S(PJ_A1 + o + 8);
                a1[mi][3] = U32S(PJ_A1 + o + 8*PJS + 8);
                a2[mi][0] = U32S(PJ_A2 + o);
                a2[mi][1] = U32S(PJ_A2 + o + 8*PJS);
                a2[mi][2] = U32S(PJ_A2 + o + 8);
                a2[mi][3] = U32S(PJ_A2 + o + 8*PJS + 8);
            }
#pragma unroll
            for (int ni = 0; ni < 4; ni++) {
                int bn = wn * 32 + ni * 8 + g;
                int bo = bn * PJS + s * 16 + 2 * tg;
                uint32_t b1[2] = {U32S(PJ_B1 + bo), U32S(PJ_B1 + bo + 8)};
                uint32_t b2[2] = {U32S(PJ_B2 + bo), U32S(PJ_B2 + bo + 8)};
#pragma unroll
                for (int mi = 0; mi < 2; mi++) {
                    mma16(acc[mi][ni], a1[mi], b1);
                    mma16(acc[mi][ni], a1[mi], b2);
                    if (sel < 2) mma16(acc[mi][ni], a2[mi], b1);
                }
            }
        }
        if (c < 31) {
            __syncthreads();
            store();
            __syncthreads();
        }
    }

#pragma unroll
    for (int mi = 0; mi < 2; mi++) {
        int row = m0 + wm * 32 + mi * 16 + g;
#pragma unroll
        for (int ni = 0; ni < 4; ni++) {
            int col = wn * 32 + ni * 8 + tg * 2;
            *(float2*)&outp[(size_t)row * H_ + col] =
                make_float2(acc[mi][ni][0], acc[mi][ni][1]);
            *(float2*)&outp[(size_t)(row + 8) * H_ + col] =
                make_float2(acc[mi][ni][2], acc[mi][ni][3]);
        }
    }
}

// ---------------------------------------------------------------------------
// Flash attention. BQ=64, BK=64. 8 warps (4m x 2n).
// QK^T: fp16 split-2, 3 products. PV: fp16 single (P, V half).
// ldmatrix fragment loads; K/V double-buffered; 1 syncthreads per tile.
// ---------------------------------------------------------------------------
#define QH1_ 0
#define QH2_ 8704
#define KH1_(b) (17408 + (b)*17408)
#define KH2_(b) (17408 + (b)*17408 + 8704)
#define VS_(b)  (52224 + (b)*8704)
#define PH_     69632
#define HEND_   74240
#define A_SMEM (HEND_*2 + 256*4)   // 149504 B

__global__ __launch_bounds__(256, 1) void attn_tc(float* __restrict__ out)
{
    extern __shared__ __half shh[];
    float* smax = (float*)(shh + HEND_);
    float* ssum = smax + 128;
    const uint32_t sb = smem_u32(shh);

    const int t   = threadIdx.x;
    const int wid = t >> 5, lane = t & 31;
    const int wm  = wid >> 1, wn = wid & 1;
    const int g   = lane >> 2, tg = lane & 3;
    const int qt  = (int)gridDim.x - 1 - (int)blockIdx.x;
    const int b   = blockIdx.y;
    const size_t base = (size_t)b * (T_ * H_);
    const float scale = 45.25483399593904f;   // sqrt(2048)

    // lane-pattern ldmatrix offsets (half indices)
    const int aoffQ = (lane & 15) * 136 + 8 * (lane >> 4);                 // A, stride 136
    const int aoffP = (lane & 15) * 72  + 8 * (lane >> 4);                 // A, stride 72
    const int boffK = ((lane & 7) + 8 * (lane >> 4)) * 136 + 8 * ((lane >> 3) & 1); // B
    const int voffV = ((lane & 7) + 8 * ((lane >> 3) & 1)) * 136 + 8 * (lane >> 4); // B trans

    // Q: 64x128, scaled + fp16 split
#pragma unroll
    for (int p = 0; p < 8; p++) {
        int idx = p * 256 + t;
        int row = idx >> 5, c4 = idx & 31;
        float4 v = *(const float4*)&g_q[base + (size_t)(qt * 64 + row) * H_ + c4 * 4];
        v.x *= scale; v.y *= scale; v.z *= scale; v.w *= scale;
        uint32_t h0, l0, h1, l1;
        split2(v.x, v.y, h0, l0);
        split2(v.z, v.w, h1, l1);
        int o = row * 136 + c4 * 4;
        *(uint32_t*)&shh[QH1_ + o]     = h0;
        *(uint32_t*)&shh[QH1_ + o + 2] = h1;
        *(uint32_t*)&shh[QH2_ + o]     = l0;
        *(uint32_t*)&shh[QH2_ + o + 2] = l1;
    }

    float of[8][4];
#pragma unroll
    for (int ni = 0; ni < 8; ni++)
#pragma unroll
        for (int r = 0; r < 4; r++) of[ni][r] = 0.f;
    float mrun0 = -INFINITY, mrun1 = -INFINITY;
    float lrun0 = 0.f, lrun1 = 0.f;

    const int r0 = wm * 16 + g;
    const int r1 = r0 + 8;
    const int ntiles = qt + 1;
    const int lrow = t >> 5, lc4 = t & 31;   // K/V loader mapping

    float4 pk[8], pv[8];
    auto fetchKV = [&](int kt) {
#pragma unroll
        for (int pp = 0; pp < 8; pp++) {
            int row = pp * 8 + lrow;
            pk[pp] = *(const float4*)&g_k[base + (size_t)(kt * 64 + row) * H_ + lc4 * 4];
            pv[pp] = *(const float4*)&g_v[base + (size_t)(kt * 64 + row) * H_ + lc4 * 4];
        }
    };
    auto storeKV = [&](int buf) {
#pragma unroll
        for (int pp = 0; pp < 8; pp++) {
            int row = pp * 8 + lrow;
            int o = row * 136 + lc4 * 4;
            float4 v = pk[pp];
            uint32_t h0, l0, h1, l1;
            split2(v.x, v.y, h0, l0);
            split2(v.z, v.w, h1, l1);
            *(uint32_t*)&shh[KH1_(buf) + o]     = h0;
            *(uint32_t*)&shh[KH1_(buf) + o + 2] = h1;
            *(uint32_t*)&shh[KH2_(buf) + o]     = l0;
            *(uint32_t*)&shh[KH2_(buf) + o + 2] = l1;
            float4 w = pv[pp];
            __half2 va = __floats2half2_rn(w.x, w.y);
            __half2 vb = __floats2half2_rn(w.z, w.w);
            uint2 u = make_uint2(*(uint32_t*)&va, *(uint32_t*)&vb);
            *(uint2*)&shh[VS_(buf) + o] = u;
        }
    };

    fetchKV(0);
    storeKV(0);
    if (ntiles > 1) fetchKV(1);
    __syncthreads();

    for (int kt = 0; kt < ntiles; kt++) {
        const int p = kt & 1;
        if (kt + 1 < ntiles) {
            storeKV(p ^ 1);
            if (kt + 2 < ntiles) fetchKV(kt + 2);
        }

        // S = Q K^T  (64x64), fp16 split-2, 3 products, ldmatrix frags
        float sf[4][4];
#pragma unroll
        for (int ni = 0; ni < 4; ni++)
#pragma unroll
            for (int r = 0; r < 4; r++) sf[ni][r] = 0.f;

        const uint32_t qb1 = sb + 2 * (QH1_ + wm * 16 * 136 + aoffQ);
        const uint32_t qb2 = sb + 2 * (QH2_ + wm * 16 * 136 + aoffQ);
        const uint32_t kb1b = sb + 2 * (KH1_(p) + wn * 32 * 136 + boffK);
        const uint32_t kb2b = sb + 2 * (KH2_(p) + wn * 32 * 136 + boffK);
#pragma unroll
        for (int ks = 0; ks < 8; ks++) {
            uint32_t qa1[4], qa2[4];
            ldsm4(qa1, qb1 + 2 * (ks * 16));
            ldsm4(qa2, qb2 + 2 * (ks * 16));
#pragma unroll
            for (int ng = 0; ng < 2; ng++) {
                uint32_t kb1[4], kb2[4];
                ldsm4(kb1, kb1b + 2 * (ng * 16 * 136 + ks * 16));
                ldsm4(kb2, kb2b + 2 * (ng * 16 * 136 + ks * 16));
                mma16(sf[2*ng],     qa1, kb1);
                mma16(sf[2*ng + 1], qa1, kb1 + 2);
                mma16(sf[2*ng],     qa1, kb2);
                mma16(sf[2*ng + 1], qa1, kb2 + 2);
                mma16(sf[2*ng],     qa2, kb1);
                mma16(sf[2*ng + 1], qa2, kb1 + 2);
            }
        }

        // causal mask: only the diagonal tile (kt == qt)
        if (kt == qt) {
#pragma unroll
            for (int ni = 0; ni < 4; ni++) {
                int col = wn * 32 + ni * 8 + tg * 2;   // local col in [0,64)
                if (col     > r0)     sf[ni][0] = -INFINITY;
                if (col + 1 > r0)     sf[ni][1] = -INFINITY;
                if (col     > r0 + 8) sf[ni][2] = -INFINITY;
                if (col + 1 > r0 + 8) sf[ni][3] = -INFINITY;
            }
        }

        // row max across this warp's 32 cols, then across the 2 n-warps (pair)
        float pm0 = -INFINITY, pm1 = -INFINITY;
#pragma unroll
        for (int ni = 0; ni < 4; ni++) {
            pm0 = fmaxf(pm0, fmaxf(sf[ni][0], sf[ni][1]));
            pm1 = fmaxf(pm1, fmaxf(sf[ni][2], sf[ni][3]));
        }
        pm0 = fmaxf(pm0, __shfl_xor_sync(0xffffffffu, pm0, 1));
        pm0 = fmaxf(pm0, __shfl_xor_sync(0xffffffffu, pm0, 2));
        pm1 = fmaxf(pm1, __shfl_xor_sync(0xffffffffu, pm1, 1));
        pm1 = fmaxf(pm1, __shfl_xor_sync(0xffffffffu, pm1, 2));
        if (tg == 0) { smax[wn * 64 + r0] = pm0; smax[wn * 64 + r1] = pm1; }
        asm volatile("bar.sync %0, 64;" :: "r"(1 + wm) : "memory");

        float m0n = fmaxf(mrun0, fmaxf(smax[r0], smax[64 + r0]));
        float m1n = fmaxf(mrun1, fmaxf(smax[r1], smax[64 + r1]));
        float f0 = __expf(mrun0 - m0n);
        float f1 = __expf(mrun1 - m1n);
        mrun0 = m0n; mrun1 = m1n;

        // exp, partial sums, write P (fp16)
        float ps0 = 0.f, ps1 = 0.f;
#pragma unroll
        for (int ni = 0; ni < 4; ni++) {
            float e0 = __expf(sf[ni][0] - m0n);
            float e1 = __expf(sf[ni][1] - m0n);
            float e2 = __expf(sf[ni][2] - m1n);
            float e3 = __expf(sf[ni][3] - m1n);
            ps0 += e0 + e1; ps1 += e2 + e3;
            int col = wn * 32 + ni * 8 + tg * 2;
            __half2 p01 = __floats2half2_rn(e0, e1);
            __half2 p23 = __floats2half2_rn(e2, e3);
            *(uint32_t*)&shh[PH_ + r0 * 72 + col] = *(uint32_t*)&p01;
            *(uint32_t*)&shh[PH_ + r1 * 72 + col] = *(uint32_t*)&p23;
        }
        ps0 += __shfl_xor_sync(0xffffffffu, ps0, 1);
        ps0 += __shfl_xor_sync(0xffffffffu, ps0, 2);
        ps1 += __shfl_xor_sync(0xffffffffu, ps1, 1);
        ps1 += __shfl_xor_sync(0xffffffffu, ps1, 2);
        if (tg == 0) { ssum[wn * 64 + r0] = ps0; ssum[wn * 64 + r1] = ps1; }

        // rescale O while the pair barrier drains
#pragma unroll
        for (int ni = 0; ni < 8; ni++) {
            of[ni][0] *= f0; of[ni][1] *= f0;
            of[ni][2] *= f1; of[ni][3] *= f1;
        }
        asm volatile("bar.sync %0, 64;" :: "r"(1 + wm) : "memory");
        lrun0 = lrun0 * f0 + ssum[r0] + ssum[64 + r0];
        lrun1 = lrun1 * f1 + ssum[r1] + ssum[64 + r1];

        // O += P V  (fp16 single), ldmatrix frags
        const uint32_t pb = sb + 2 * (PH_ + wm * 16 * 72 + aoffP);
        const uint32_t vbb = sb + 2 * (VS_(p) + wn * 64 + voffV);
#pragma unroll
        for (int ks = 0; ks < 4; ks++) {
            uint32_t pa[4];
            ldsm4(pa, pb + 2 * (ks * 16));
#pragma unroll
            for (int ng = 0; ng < 4; ng++) {
                uint32_t vb[4];
                ldsm4t(vb, vbb + 2 * (ks * 16 * 136 + ng * 16));
                mma16(of[2*ng],     pa, vb);
                mma16(of[2*ng + 1], pa, vb + 2);
            }
        }

        __syncthreads();   // buf p^1 stores visible; buf p free for overwrite
    }

    // epilogue
    float inv0 = 1.f / lrun0;
    float inv1 = 1.f / lrun1;
    int grow = qt * 64 + r0;
#pragma unroll
    for (int ni = 0; ni < 8; ni++) {
        int col = wn * 64 + ni * 8 + tg * 2;
        *(float2*)&out[base + (size_t)grow * H_ + col] =
            make_float2(of[ni][0] * inv0, of[ni][1] * inv0);
        *(float2*)&out[base + (size_t)(grow + 8) * H_ + col] =
            make_float2(of[ni][2] * inv1, of[ni][3] * inv1);
    }
}

// ---------------------------------------------------------------------------
extern "C" void kernel_launch(void* const* d_in, const int* in_sizes, int n_in,
                              void* d_out, int out_size)
{
    const float* x  = (const float*)d_in[0];
    const float* Wq = (const float*)d_in[1];
    const float* Wk = (const float*)d_in[2];
    const float* Wv = (const float*)d_in[3];
    float* out = (float*)d_out;

    prep_w<<<dim3(E_/32, H_/32, 3), 256>>>(Wq, Wk, Wv);

    cudaFuncSetAttribute(proj_tc,
                         cudaFuncAttributeMaxDynamicSharedMemorySize, PJ_SMEM);
    proj_tc<<<dim3(BT_/64, 3), 256, PJ_SMEM>>>(x);

    cudaFuncSetAttribute(attn_tc,
                         cudaFuncAttributeMaxDynamicSharedMemorySize, A_SMEM);
    attn_tc<<<dim3(T_/64, B_), 256, A_SMEM>>>(out);
}